// round 1
// baseline (speedup 1.0000x reference)
#include <cuda_runtime.h>
#include <math.h>

// Problem constants
#define B_   4
#define T_   2048
#define C_   2048
#define H_   16
#define D_   128
#define BH_  (B_ * H_)        // 64
#define M_   (B_ * T_)        // 8192
#define N3_  (3 * C_)         // 6144

// ---------------- scratch (device globals; no allocation allowed) ----------
__device__ float g_qkv[M_ * N3_];          // [8192, 6144]   201 MB
__device__ float g_q[BH_ * T_ * D_];       // [64, 2048, 128] 67 MB
__device__ float g_k[BH_ * T_ * D_];
__device__ float g_v[BH_ * T_ * D_];
__device__ float g_ctx[M_ * C_];           // [8192, 2048]    67 MB
__device__ float g_cos[T_ * 64];
__device__ float g_sin[T_ * 64];

// ---------------------------------------------------------------------------
// SGEMM: C = A[M,K] @ B[K,N] (+ bias). BM=BN=128, BK=16, 256 thr, 8x8 micro.
// ---------------------------------------------------------------------------
__global__ void __launch_bounds__(256) sgemm_kernel(
    const float* __restrict__ A, const float* __restrict__ Bm,
    const float* __restrict__ bias, float* __restrict__ C,
    int M, int N, int K)
{
    constexpr int BK = 16;
    constexpr int ASTR = 132;                 // padded stride for transposed A tile
    __shared__ __align__(16) float As[BK * ASTR];
    __shared__ __align__(16) float Bs[BK * 128];

    const int tid = threadIdx.x;
    const int tx = tid & 15, ty = tid >> 4;
    const int row0 = blockIdx.y * 128;
    const int col0 = blockIdx.x * 128;

    float acc[8][8];
#pragma unroll
    for (int i = 0; i < 8; i++)
#pragma unroll
        for (int j = 0; j < 8; j++) acc[i][j] = 0.f;

    for (int kb = 0; kb < K; kb += BK) {
#pragma unroll
        for (int u = 0; u < 2; u++) {
            int idx = u * 256 + tid;          // 0..511 float4 slots
            // A tile: 128 rows x 16 cols -> transposed into As[k][m]
            int r  = idx >> 2, c4 = idx & 3;
            float4 av = *(const float4*)&A[(size_t)(row0 + r) * K + kb + c4 * 4];
            As[(c4 * 4 + 0) * ASTR + r] = av.x;
            As[(c4 * 4 + 1) * ASTR + r] = av.y;
            As[(c4 * 4 + 2) * ASTR + r] = av.z;
            As[(c4 * 4 + 3) * ASTR + r] = av.w;
            // B tile: 16 rows x 128 cols, row-major
            int rb = idx >> 5, cb = idx & 31;
            *(float4*)&Bs[rb * 128 + cb * 4] =
                *(const float4*)&Bm[(size_t)(kb + rb) * N + col0 + cb * 4];
        }
        __syncthreads();

#pragma unroll
        for (int k = 0; k < BK; k++) {
            float a[8], b[8];
            *(float4*)&a[0] = *(float4*)&As[k * ASTR + ty * 8];
            *(float4*)&a[4] = *(float4*)&As[k * ASTR + ty * 8 + 4];
            *(float4*)&b[0] = *(float4*)&Bs[k * 128 + tx * 8];
            *(float4*)&b[4] = *(float4*)&Bs[k * 128 + tx * 8 + 4];
#pragma unroll
            for (int i = 0; i < 8; i++)
#pragma unroll
                for (int j = 0; j < 8; j++) acc[i][j] += a[i] * b[j];
        }
        __syncthreads();
    }

#pragma unroll
    for (int i = 0; i < 8; i++) {
        int r = row0 + ty * 8 + i;
#pragma unroll
        for (int j4 = 0; j4 < 2; j4++) {
            int col = col0 + tx * 8 + j4 * 4;
            float4 o;
            o.x = acc[i][j4 * 4 + 0];
            o.y = acc[i][j4 * 4 + 1];
            o.z = acc[i][j4 * 4 + 2];
            o.w = acc[i][j4 * 4 + 3];
            if (bias) {
                o.x += bias[col + 0]; o.y += bias[col + 1];
                o.z += bias[col + 2]; o.w += bias[col + 3];
            }
            *(float4*)&C[(size_t)r * N + col] = o;
        }
    }
}

// ---------------------------------------------------------------------------
// RoPE table: cos/sin of the fp32-rounded angle (matches reference rounding),
// evaluated with double-precision trig for accuracy.
// ---------------------------------------------------------------------------
__global__ void rope_table_kernel()
{
    int g = blockIdx.x * blockDim.x + threadIdx.x;   // T_*64 threads
    if (g >= T_ * 64) return;
    int t = g >> 6, i = g & 63;
    double invf = pow(10000.0, -(double)i / 64.0);
    float  angf = (float)t * (float)invf;            // fp32 rounding, like jnp
    double ang  = (double)angf;
    g_cos[g] = (float)cos(ang);
    g_sin[g] = (float)sin(ang);
}

// ---------------------------------------------------------------------------
// RoPE + split/transpose: g_qkv[B,T,3C] -> g_q/g_k/g_v[BH,T,D]
// ---------------------------------------------------------------------------
__global__ void __launch_bounds__(256) rope_kernel()
{
    int g = blockIdx.x * 256 + threadIdx.x;          // BH_*T_*D_ = 16.7M threads
    int d  = g & 127;
    int t  = (g >> 7) & 2047;
    int bh = g >> 18;
    int b  = bh >> 4, h = bh & 15;

    size_t src = ((size_t)(b * T_ + t)) * N3_ + h * D_ + d;
    int dp = (d + 64) & 127;
    size_t srcp = src - d + dp;

    float qa = g_qkv[src];
    float ka = g_qkv[src + C_];
    float va = g_qkv[src + 2 * C_];
    float qb = g_qkv[srcp];
    float kb = g_qkv[srcp + C_];

    float sgn = (d < 64) ? -1.f : 1.f;
    int i = d & 63;
    float c = g_cos[t * 64 + i];
    float s = g_sin[t * 64 + i];

    size_t dst = ((size_t)bh * T_ + t) * D_ + d;
    g_q[dst] = qa * c + sgn * qb * s;
    g_k[dst] = ka * c + sgn * kb * s;
    g_v[dst] = va;
}

// ---------------------------------------------------------------------------
// Flash attention (causal): block = (qtile 64 rows, one bh). 256 threads.
// S tile 64x64, online softmax, O[64][128] in registers (4x8/thread).
// Writes output in [B,T,C] layout directly.
// ---------------------------------------------------------------------------
#define QK_STR 65
#define SS_STR 65
#define ATTN_SMEM_FLOATS (128*QK_STR*2 + 64*128 + 64*SS_STR + 192)
#define ATTN_SMEM_BYTES  (ATTN_SMEM_FLOATS * 4)

__global__ void __launch_bounds__(256) attn_kernel()
{
    const int tid = threadIdx.x;
    const int tx = tid & 15, ty = tid >> 4;
    const int qt = blockIdx.x;                       // 0..31
    const int bh = blockIdx.y;                       // 0..63
    const int q0 = qt * 64;

    extern __shared__ float sm[];
    float* Qs = sm;                                  // [128][65]  (d-major)
    float* Ks = sm + 128 * QK_STR;                   // [128][65]
    float* Vs = Ks + 128 * QK_STR;                   // [64][128]  (row-major)
    float* Ss = Vs + 64 * 128;                       // [64][65]
    float* mrow = Ss + 64 * SS_STR;
    float* lrow = mrow + 64;
    float* arow = lrow + 64;

    const float* Qg = g_q + (size_t)bh * T_ * D_;
    const float* Kg = g_k + (size_t)bh * T_ * D_;
    const float* Vg = g_v + (size_t)bh * T_ * D_;

    // Load Q tile (transposed to [d][q])
#pragma unroll
    for (int u = 0; u < 8; u++) {
        int idx = u * 256 + tid;                     // 0..2047 float4 slots
        int r = idx >> 5, c4 = idx & 31;
        float4 v = *(const float4*)&Qg[(size_t)(q0 + r) * D_ + c4 * 4];
        Qs[(c4 * 4 + 0) * QK_STR + r] = v.x;
        Qs[(c4 * 4 + 1) * QK_STR + r] = v.y;
        Qs[(c4 * 4 + 2) * QK_STR + r] = v.z;
        Qs[(c4 * 4 + 3) * QK_STR + r] = v.w;
    }
    if (tid < 64) { mrow[tid] = -1e30f; lrow[tid] = 0.f; }

    float o[4][8];
#pragma unroll
    for (int i = 0; i < 4; i++)
#pragma unroll
        for (int j = 0; j < 8; j++) o[i][j] = 0.f;

    __syncthreads();

    for (int kt = 0; kt <= qt; kt++) {
        const int k0 = kt * 64;
        // Load K (transposed) and V (row-major)
#pragma unroll
        for (int u = 0; u < 8; u++) {
            int idx = u * 256 + tid;
            int r = idx >> 5, c4 = idx & 31;
            float4 kv = *(const float4*)&Kg[(size_t)(k0 + r) * D_ + c4 * 4];
            Ks[(c4 * 4 + 0) * QK_STR + r] = kv.x;
            Ks[(c4 * 4 + 1) * QK_STR + r] = kv.y;
            Ks[(c4 * 4 + 2) * QK_STR + r] = kv.z;
            Ks[(c4 * 4 + 3) * QK_STR + r] = kv.w;
            *(float4*)&Vs[r * 128 + c4 * 4] =
                *(const float4*)&Vg[(size_t)(k0 + r) * D_ + c4 * 4];
        }
        __syncthreads();

        // S = Q K^T  (4x4 per thread)
        float s[4][4];
#pragma unroll
        for (int i = 0; i < 4; i++)
#pragma unroll
            for (int j = 0; j < 4; j++) s[i][j] = 0.f;

#pragma unroll 4
        for (int d = 0; d < 128; d++) {
            float qa[4], ka[4];
#pragma unroll
            for (int i = 0; i < 4; i++) qa[i] = Qs[d * QK_STR + ty * 4 + i];
#pragma unroll
            for (int j = 0; j < 4; j++) ka[j] = Ks[d * QK_STR + tx * 4 + j];
#pragma unroll
            for (int i = 0; i < 4; i++)
#pragma unroll
                for (int j = 0; j < 4; j++) s[i][j] += qa[i] * ka[j];
        }

        const float scale = 0.08838834764831845f;    // 1/sqrt(128)
        const bool diag = (kt == qt);
#pragma unroll
        for (int i = 0; i < 4; i++)
#pragma unroll
            for (int j = 0; j < 4; j++) {
                float v = s[i][j] * scale;
                if (diag && (tx * 4 + j) > (ty * 4 + i)) v = -1e30f;
                Ss[(ty * 4 + i) * SS_STR + tx * 4 + j] = v;
            }
        __syncthreads();

        // Online softmax update (64 threads, one row each)
        if (tid < 64) {
            int r = tid;
            float mo = mrow[r];
            float tm = mo;
#pragma unroll 8
            for (int k = 0; k < 64; k++) tm = fmaxf(tm, Ss[r * SS_STR + k]);
            float a = __expf(mo - tm);
            float sum = 0.f;
#pragma unroll 8
            for (int k = 0; k < 64; k++) {
                float p = __expf(Ss[r * SS_STR + k] - tm);
                Ss[r * SS_STR + k] = p;
                sum += p;
            }
            lrow[r] = lrow[r] * a + sum;
            mrow[r] = tm;
            arow[r] = a;
        }
        __syncthreads();

        // O = O*alpha + P V  (4x8 per thread)
        float al[4];
#pragma unroll
        for (int i = 0; i < 4; i++) al[i] = arow[ty * 4 + i];
#pragma unroll
        for (int i = 0; i < 4; i++)
#pragma unroll
            for (int j = 0; j < 8; j++) o[i][j] *= al[i];

#pragma unroll 4
        for (int k = 0; k < 64; k++) {
            float p[4], vv[8];
#pragma unroll
            for (int i = 0; i < 4; i++) p[i] = Ss[(ty * 4 + i) * SS_STR + k];
            *(float4*)&vv[0] = *(float4*)&Vs[k * 128 + tx * 8];
            *(float4*)&vv[4] = *(float4*)&Vs[k * 128 + tx * 8 + 4];
#pragma unroll
            for (int i = 0; i < 4; i++)
#pragma unroll
                for (int j = 0; j < 8; j++) o[i][j] += p[i] * vv[j];
        }
        __syncthreads();
    }

    // Epilogue: normalize and write to [B,T,C]
    const int b = bh >> 4, h = bh & 15;
#pragma unroll
    for (int i = 0; i < 4; i++) {
        int r = ty * 4 + i;
        float inv = 1.0f / lrow[r];
        int q = q0 + r;
        float* dst = g_ctx + ((size_t)(b * T_ + q)) * C_ + h * D_ + tx * 8;
        float4 w0, w1;
        w0.x = o[i][0] * inv; w0.y = o[i][1] * inv;
        w0.z = o[i][2] * inv; w0.w = o[i][3] * inv;
        w1.x = o[i][4] * inv; w1.y = o[i][5] * inv;
        w1.z = o[i][6] * inv; w1.w = o[i][7] * inv;
        *(float4*)dst = w0;
        *(float4*)(dst + 4) = w1;
    }
}

// ---------------------------------------------------------------------------
extern "C" void kernel_launch(void* const* d_in, const int* in_sizes, int n_in,
                              void* d_out, int out_size)
{
    // Identify inputs by element count (robust to ordering)
    const float* x = nullptr; const float* w_qkv = nullptr;
    const float* w_proj = nullptr; const float* b_proj = nullptr;
    for (int i = 0; i < n_in; i++) {
        switch (in_sizes[i]) {
            case M_ * C_:       x      = (const float*)d_in[i]; break;  // 16.7M
            case C_ * N3_:      w_qkv  = (const float*)d_in[i]; break;  // 12.6M
            case C_ * C_:       w_proj = (const float*)d_in[i]; break;  // 4.2M
            case C_:            b_proj = (const float*)d_in[i]; break;  // 2048
        }
    }
    float* out = (float*)d_out;

    void *p_qkv, *p_ctx;
    cudaGetSymbolAddress(&p_qkv, g_qkv);
    cudaGetSymbolAddress(&p_ctx, g_ctx);

    // 1) QKV GEMM: [8192,2048] @ [2048,6144]
    sgemm_kernel<<<dim3(N3_ / 128, M_ / 128), 256>>>(
        x, w_qkv, nullptr, (float*)p_qkv, M_, N3_, C_);

    // 2) RoPE trig table
    rope_table_kernel<<<(T_ * 64 + 255) / 256, 256>>>();

    // 3) RoPE + transpose split
    rope_kernel<<<(BH_ * T_ * D_) / 256, 256>>>();

    // 4) Causal flash attention
    cudaFuncSetAttribute(attn_kernel,
                         cudaFuncAttributeMaxDynamicSharedMemorySize,
                         ATTN_SMEM_BYTES);
    attn_kernel<<<dim3(T_ / 64, BH_), 256, ATTN_SMEM_BYTES>>>();

    // 5) Projection GEMM + bias: [8192,2048] @ [2048,2048] -> out
    sgemm_kernel<<<dim3(C_ / 128, M_ / 128), 256>>>(
        (const float*)p_ctx, w_proj, b_proj, out, M_, C_, C_);
}

// round 3
// speedup vs baseline: 1.7780x; 1.7780x over previous
#include <cuda_runtime.h>
#include <cuda_bf16.h>
#include <math.h>
#include <stdint.h>

// Problem constants
#define B_   4
#define T_   2048
#define C_   2048
#define H_   16
#define D_   128
#define BH_  (B_ * H_)        // 64
#define M_   (B_ * T_)        // 8192
#define N3_  (3 * C_)         // 6144

// ============================ helpers ======================================
__device__ __forceinline__ uint32_t smem_u32(const void* p) {
    uint32_t a;
    asm("{ .reg .u64 t; cvta.to.shared.u64 t, %1; cvt.u32.u64 %0, t; }"
        : "=r"(a) : "l"(p));
    return a;
}
#define CP_ASYNC16(saddr, gptr) \
    asm volatile("cp.async.cg.shared.global [%0], [%1], 16;" \
                 :: "r"(saddr), "l"(gptr) : "memory")
#define CP_COMMIT() asm volatile("cp.async.commit_group;" ::: "memory")
#define CP_WAIT1()  asm volatile("cp.async.wait_group 1;" ::: "memory")

#define LDMATRIX_X4(r0, r1, r2, r3, addr) \
    asm volatile("ldmatrix.sync.aligned.m8n8.x4.shared.b16 {%0,%1,%2,%3}, [%4];" \
                 : "=r"(r0), "=r"(r1), "=r"(r2), "=r"(r3) : "r"(addr))
#define LDMATRIX_X2(r0, r1, addr) \
    asm volatile("ldmatrix.sync.aligned.m8n8.x2.shared.b16 {%0,%1}, [%2];" \
                 : "=r"(r0), "=r"(r1) : "r"(addr))
#define MMA_BF16(c, a, b) \
    asm volatile("mma.sync.aligned.m16n8k16.row.col.f32.bf16.bf16.f32 " \
                 "{%0,%1,%2,%3}, {%4,%5,%6,%7}, {%8,%9}, {%0,%1,%2,%3};" \
                 : "+f"((c)[0]), "+f"((c)[1]), "+f"((c)[2]), "+f"((c)[3]) \
                 : "r"((a)[0]), "r"((a)[1]), "r"((a)[2]), "r"((a)[3]), \
                   "r"((b)[0]), "r"((b)[1]))

// ---------------- scratch (device globals; no allocation allowed) ----------
__device__ float g_qkv[M_ * N3_];          // [8192, 6144] fp32
__device__ float g_q[BH_ * T_ * D_];
__device__ float g_k[BH_ * T_ * D_];
__device__ float g_v[BH_ * T_ * D_];
__device__ float g_ctx[M_ * C_];           // attention output, [B,T,C] fp32
__device__ float g_cos[T_ * 64];
__device__ float g_sin[T_ * 64];
// split-bf16 operands
__device__ __nv_bfloat16 gx_hi[M_ * C_],  gx_lo[M_ * C_];      // activations [M,K]
__device__ __nv_bfloat16 gcx_hi[M_ * C_], gcx_lo[M_ * C_];     // ctx [M,K]
__device__ __nv_bfloat16 gwq_hi[N3_ * C_], gwq_lo[N3_ * C_];   // W_qkv^T [N,K]
__device__ __nv_bfloat16 gwp_hi[C_ * C_],  gwp_lo[C_ * C_];    // W_proj^T [N,K]

// ---------------------------------------------------------------------------
// split fp32 -> (hi, lo) bf16, elementwise (vectorized by 4)
// ---------------------------------------------------------------------------
__global__ void __launch_bounds__(256) split_kernel(
    const float* __restrict__ in, __nv_bfloat16* __restrict__ hi,
    __nv_bfloat16* __restrict__ lo, int n4)
{
    int i = blockIdx.x * 256 + threadIdx.x;
    if (i >= n4) return;
    float4 v = ((const float4*)in)[i];
    __nv_bfloat16 h0 = __float2bfloat16(v.x), h1 = __float2bfloat16(v.y);
    __nv_bfloat16 h2 = __float2bfloat16(v.z), h3 = __float2bfloat16(v.w);
    __nv_bfloat16 l0 = __float2bfloat16(v.x - __bfloat162float(h0));
    __nv_bfloat16 l1 = __float2bfloat16(v.y - __bfloat162float(h1));
    __nv_bfloat16 l2 = __float2bfloat16(v.z - __bfloat162float(h2));
    __nv_bfloat16 l3 = __float2bfloat16(v.w - __bfloat162float(h3));
    __nv_bfloat162* hp = (__nv_bfloat162*)hi;
    __nv_bfloat162* lp = (__nv_bfloat162*)lo;
    hp[i * 2 + 0] = __nv_bfloat162(h0, h1);
    hp[i * 2 + 1] = __nv_bfloat162(h2, h3);
    lp[i * 2 + 0] = __nv_bfloat162(l0, l1);
    lp[i * 2 + 1] = __nv_bfloat162(l2, l3);
}

// ---------------------------------------------------------------------------
// transpose + split: W[K,N] fp32 -> Th/Tl[N,K] bf16
// ---------------------------------------------------------------------------
__global__ void __launch_bounds__(256) transpose_split_kernel(
    const float* __restrict__ W, __nv_bfloat16* __restrict__ Th,
    __nv_bfloat16* __restrict__ Tl, int K, int N)
{
    __shared__ float t[32][33];
    int bn = blockIdx.x * 32;
    int bk = blockIdx.y * 32;
    int x = threadIdx.x, y = threadIdx.y;       // 32 x 8
#pragma unroll
    for (int i = 0; i < 32; i += 8)
        t[y + i][x] = W[(size_t)(bk + y + i) * N + bn + x];
    __syncthreads();
#pragma unroll
    for (int i = 0; i < 32; i += 8) {
        float v = t[x][y + i];                  // = W[bk+x][bn+y+i]
        __nv_bfloat16 h = __float2bfloat16(v);
        __nv_bfloat16 l = __float2bfloat16(v - __bfloat162float(h));
        size_t o = (size_t)(bn + y + i) * K + bk + x;
        Th[o] = h; Tl[o] = l;
    }
}

// ---------------------------------------------------------------------------
// HMMA GEMM: C[M,N] = A[M,K] @ B[N,K]^T, split-bf16 x3 (hi*hi + hi*lo + lo*hi)
// CTA 128x128, BK=64, 2-stage cp.async, 8 warps (2x4), warp tile 64x32.
// ---------------------------------------------------------------------------
#define STG_BYTES 65536
#define OFF_AH 0
#define OFF_AL 16384
#define OFF_BH 32768
#define OFF_BL 49152
#define GEMM_SMEM (2 * STG_BYTES)

__device__ __forceinline__ void gemm_load_stage(
    uint32_t sb, int stage,
    const __nv_bfloat16* __restrict__ Ah, const __nv_bfloat16* __restrict__ Al,
    const __nv_bfloat16* __restrict__ Bh, const __nv_bfloat16* __restrict__ Bl,
    int row0, int col0, int kb, int K, int tid)
{
    uint32_t st = sb + stage * STG_BYTES;
    const int k0 = kb * 64;
#pragma unroll
    for (int u = 0; u < 4; u++) {
        int idx = u * 256 + tid;                 // 1024 16B chunks per operand
        int r = idx >> 3, c = idx & 7;
        uint32_t sw = (uint32_t)(r * 128 + ((c ^ (r & 7)) << 4));
        size_t ga = (size_t)(row0 + r) * K + k0 + c * 8;
        size_t gb = (size_t)(col0 + r) * K + k0 + c * 8;
        CP_ASYNC16(st + OFF_AH + sw, Ah + ga);
        CP_ASYNC16(st + OFF_AL + sw, Al + ga);
        CP_ASYNC16(st + OFF_BH + sw, Bh + gb);
        CP_ASYNC16(st + OFF_BL + sw, Bl + gb);
    }
}

__global__ void __launch_bounds__(256) gemm_mma_kernel(
    const __nv_bfloat16* __restrict__ Ah, const __nv_bfloat16* __restrict__ Al,
    const __nv_bfloat16* __restrict__ Bh, const __nv_bfloat16* __restrict__ Bl,
    float* __restrict__ Cout, const float* __restrict__ bias, int N, int K)
{
    extern __shared__ __align__(1024) char smem[];
    const uint32_t sb = smem_u32(smem);
    const int tid = threadIdx.x;
    const int wid = tid >> 5, lane = tid & 31;
    const int wr = wid >> 2, wc = wid & 3;       // warp grid 2 x 4
    const int col0 = blockIdx.x * 128;
    const int row0 = blockIdx.y * 128;
    const int NK = K / 64;

    float acc[4][4][4];
#pragma unroll
    for (int i = 0; i < 4; i++)
#pragma unroll
        for (int j = 0; j < 4; j++)
#pragma unroll
            for (int k = 0; k < 4; k++) acc[i][j][k] = 0.f;

    gemm_load_stage(sb, 0, Ah, Al, Bh, Bl, row0, col0, 0, K, tid);
    CP_COMMIT();
    gemm_load_stage(sb, 1, Ah, Al, Bh, Bl, row0, col0, 1, K, tid);
    CP_COMMIT();

    // Precompute per-lane ldmatrix base offsets (within a stage)
    const int a_row = wr * 64 + (lane & 15);              // + mt*16
    const int b_row = wc * 32 + (lane & 7);               // + nt*8
    const int a_cg  = (lane >> 4);                        // chunk add 0/1
    const int b_cg  = ((lane >> 3) & 1);

    for (int kb = 0; kb < NK; kb++) {
        CP_WAIT1();
        __syncthreads();
        uint32_t st = sb + (kb & 1) * STG_BYTES;

#pragma unroll
        for (int ks = 0; ks < 4; ks++) {
            uint32_t ah[4][4], alr[4][4], bh[4][2], bl[4][2];
#pragma unroll
            for (int mt = 0; mt < 4; mt++) {
                int r = a_row + mt * 16;
                int c = ks * 2 + a_cg;
                uint32_t ad = st + (uint32_t)(r * 128 + ((c ^ (r & 7)) << 4));
                LDMATRIX_X4(ah[mt][0], ah[mt][1], ah[mt][2], ah[mt][3], ad + OFF_AH);
                LDMATRIX_X4(alr[mt][0], alr[mt][1], alr[mt][2], alr[mt][3], ad + OFF_AL);
            }
#pragma unroll
            for (int nt = 0; nt < 4; nt++) {
                int n = b_row + nt * 8;
                int c = ks * 2 + b_cg;
                uint32_t bd = st + (uint32_t)(n * 128 + ((c ^ (n & 7)) << 4));
                LDMATRIX_X2(bh[nt][0], bh[nt][1], bd + OFF_BH);
                LDMATRIX_X2(bl[nt][0], bl[nt][1], bd + OFF_BL);
            }
#pragma unroll
            for (int mt = 0; mt < 4; mt++)
#pragma unroll
                for (int nt = 0; nt < 4; nt++) {
                    MMA_BF16(acc[mt][nt], ah[mt], bh[nt]);
                    MMA_BF16(acc[mt][nt], ah[mt], bl[nt]);
                    MMA_BF16(acc[mt][nt], alr[mt], bh[nt]);
                }
        }
        __syncthreads();
        if (kb + 2 < NK)
            gemm_load_stage(sb, kb & 1, Ah, Al, Bh, Bl, row0, col0, kb + 2, K, tid);
        CP_COMMIT();
    }

    // Epilogue
    const int er = lane >> 2;            // 0..7
    const int ec = (lane & 3) * 2;       // 0,2,4,6
#pragma unroll
    for (int mt = 0; mt < 4; mt++) {
        int row = row0 + wr * 64 + mt * 16 + er;
#pragma unroll
        for (int nt = 0; nt < 4; nt++) {
            int col = col0 + wc * 32 + nt * 8 + ec;
            float b0 = 0.f, b1 = 0.f;
            if (bias) { b0 = bias[col]; b1 = bias[col + 1]; }
            float2 v0, v1;
            v0.x = acc[mt][nt][0] + b0; v0.y = acc[mt][nt][1] + b1;
            v1.x = acc[mt][nt][2] + b0; v1.y = acc[mt][nt][3] + b1;
            *(float2*)&Cout[(size_t)row * N + col] = v0;
            *(float2*)&Cout[(size_t)(row + 8) * N + col] = v1;
        }
    }
}

// ---------------------------------------------------------------------------
// RoPE table: cos/sin of the fp32-rounded angle (matches reference rounding)
// ---------------------------------------------------------------------------
__global__ void rope_table_kernel()
{
    int g = blockIdx.x * blockDim.x + threadIdx.x;
    if (g >= T_ * 64) return;
    int t = g >> 6, i = g & 63;
    double invf = pow(10000.0, -(double)i / 64.0);
    float  angf = (float)t * (float)invf;
    double ang  = (double)angf;
    g_cos[g] = (float)cos(ang);
    g_sin[g] = (float)sin(ang);
}

// ---------------------------------------------------------------------------
// RoPE + split/transpose: g_qkv[B,T,3C] -> g_q/g_k/g_v[BH,T,D]
// ---------------------------------------------------------------------------
__global__ void __launch_bounds__(256) rope_kernel()
{
    int g = blockIdx.x * 256 + threadIdx.x;
    int d  = g & 127;
    int t  = (g >> 7) & 2047;
    int bh = g >> 18;
    int b  = bh >> 4, h = bh & 15;

    size_t src = ((size_t)(b * T_ + t)) * N3_ + h * D_ + d;
    int dp = (d + 64) & 127;
    size_t srcp = src - d + dp;

    float qa = g_qkv[src];
    float ka = g_qkv[src + C_];
    float va = g_qkv[src + 2 * C_];
    float qb = g_qkv[srcp];
    float kb = g_qkv[srcp + C_];

    float sgn = (d < 64) ? -1.f : 1.f;
    int i = d & 63;
    float c = g_cos[t * 64 + i];
    float s = g_sin[t * 64 + i];

    size_t dst = ((size_t)bh * T_ + t) * D_ + d;
    g_q[dst] = qa * c + sgn * qb * s;
    g_k[dst] = ka * c + sgn * kb * s;
    g_v[dst] = va;
}

// ---------------------------------------------------------------------------
// Flash attention (causal), fp32, unchanged from round 1 (passing baseline).
// ---------------------------------------------------------------------------
#define QK_STR 65
#define SS_STR 65
#define ATTN_SMEM_FLOATS (128*QK_STR*2 + 64*128 + 64*SS_STR + 192)
#define ATTN_SMEM_BYTES  (ATTN_SMEM_FLOATS * 4)

__global__ void __launch_bounds__(256) attn_kernel()
{
    const int tid = threadIdx.x;
    const int tx = tid & 15, ty = tid >> 4;
    const int qt = blockIdx.x;
    const int bh = blockIdx.y;
    const int q0 = qt * 64;

    extern __shared__ float sm[];
    float* Qs = sm;
    float* Ks = sm + 128 * QK_STR;
    float* Vs = Ks + 128 * QK_STR;
    float* Ss = Vs + 64 * 128;
    float* mrow = Ss + 64 * SS_STR;
    float* lrow = mrow + 64;
    float* arow = lrow + 64;

    const float* Qg = g_q + (size_t)bh * T_ * D_;
    const float* Kg = g_k + (size_t)bh * T_ * D_;
    const float* Vg = g_v + (size_t)bh * T_ * D_;

#pragma unroll
    for (int u = 0; u < 8; u++) {
        int idx = u * 256 + tid;
        int r = idx >> 5, c4 = idx & 31;
        float4 v = *(const float4*)&Qg[(size_t)(q0 + r) * D_ + c4 * 4];
        Qs[(c4 * 4 + 0) * QK_STR + r] = v.x;
        Qs[(c4 * 4 + 1) * QK_STR + r] = v.y;
        Qs[(c4 * 4 + 2) * QK_STR + r] = v.z;
        Qs[(c4 * 4 + 3) * QK_STR + r] = v.w;
    }
    if (tid < 64) { mrow[tid] = -1e30f; lrow[tid] = 0.f; }

    float o[4][8];
#pragma unroll
    for (int i = 0; i < 4; i++)
#pragma unroll
        for (int j = 0; j < 8; j++) o[i][j] = 0.f;

    __syncthreads();

    for (int kt = 0; kt <= qt; kt++) {
        const int k0 = kt * 64;
#pragma unroll
        for (int u = 0; u < 8; u++) {
            int idx = u * 256 + tid;
            int r = idx >> 5, c4 = idx & 31;
            float4 kv = *(const float4*)&Kg[(size_t)(k0 + r) * D_ + c4 * 4];
            Ks[(c4 * 4 + 0) * QK_STR + r] = kv.x;
            Ks[(c4 * 4 + 1) * QK_STR + r] = kv.y;
            Ks[(c4 * 4 + 2) * QK_STR + r] = kv.z;
            Ks[(c4 * 4 + 3) * QK_STR + r] = kv.w;
            *(float4*)&Vs[r * 128 + c4 * 4] =
                *(const float4*)&Vg[(size_t)(k0 + r) * D_ + c4 * 4];
        }
        __syncthreads();

        float s[4][4];
#pragma unroll
        for (int i = 0; i < 4; i++)
#pragma unroll
            for (int j = 0; j < 4; j++) s[i][j] = 0.f;

#pragma unroll 4
        for (int d = 0; d < 128; d++) {
            float qa[4], ka[4];
#pragma unroll
            for (int i = 0; i < 4; i++) qa[i] = Qs[d * QK_STR + ty * 4 + i];
#pragma unroll
            for (int j = 0; j < 4; j++) ka[j] = Ks[d * QK_STR + tx * 4 + j];
#pragma unroll
            for (int i = 0; i < 4; i++)
#pragma unroll
                for (int j = 0; j < 4; j++) s[i][j] += qa[i] * ka[j];
        }

        const float scale = 0.08838834764831845f;
        const bool diag = (kt == qt);
#pragma unroll
        for (int i = 0; i < 4; i++)
#pragma unroll
            for (int j = 0; j < 4; j++) {
                float v = s[i][j] * scale;
                if (diag && (tx * 4 + j) > (ty * 4 + i)) v = -1e30f;
                Ss[(ty * 4 + i) * SS_STR + tx * 4 + j] = v;
            }
        __syncthreads();

        if (tid < 64) {
            int r = tid;
            float mo = mrow[r];
            float tm = mo;
#pragma unroll 8
            for (int k = 0; k < 64; k++) tm = fmaxf(tm, Ss[r * SS_STR + k]);
            float a = __expf(mo - tm);
            float sum = 0.f;
#pragma unroll 8
            for (int k = 0; k < 64; k++) {
                float p = __expf(Ss[r * SS_STR + k] - tm);
                Ss[r * SS_STR + k] = p;
                sum += p;
            }
            lrow[r] = lrow[r] * a + sum;
            mrow[r] = tm;
            arow[r] = a;
        }
        __syncthreads();

        float al[4];
#pragma unroll
        for (int i = 0; i < 4; i++) al[i] = arow[ty * 4 + i];
#pragma unroll
        for (int i = 0; i < 4; i++)
#pragma unroll
            for (int j = 0; j < 8; j++) o[i][j] *= al[i];

#pragma unroll 4
        for (int k = 0; k < 64; k++) {
            float p[4], vv[8];
#pragma unroll
            for (int i = 0; i < 4; i++) p[i] = Ss[(ty * 4 + i) * SS_STR + k];
            *(float4*)&vv[0] = *(float4*)&Vs[k * 128 + tx * 8];
            *(float4*)&vv[4] = *(float4*)&Vs[k * 128 + tx * 8 + 4];
#pragma unroll
            for (int i = 0; i < 4; i++)
#pragma unroll
                for (int j = 0; j < 8; j++) o[i][j] += p[i] * vv[j];
        }
        __syncthreads();
    }

    const int b = bh >> 4, h = bh & 15;
#pragma unroll
    for (int i = 0; i < 4; i++) {
        int r = ty * 4 + i;
        float inv = 1.0f / lrow[r];
        int q = q0 + r;
        float* dst = g_ctx + ((size_t)(b * T_ + q)) * C_ + h * D_ + tx * 8;
        float4 w0, w1;
        w0.x = o[i][0] * inv; w0.y = o[i][1] * inv;
        w0.z = o[i][2] * inv; w0.w = o[i][3] * inv;
        w1.x = o[i][4] * inv; w1.y = o[i][5] * inv;
        w1.z = o[i][6] * inv; w1.w = o[i][7] * inv;
        *(float4*)dst = w0;
        *(float4*)(dst + 4) = w1;
    }
}

// ---------------------------------------------------------------------------
extern "C" void kernel_launch(void* const* d_in, const int* in_sizes, int n_in,
                              void* d_out, int out_size)
{
    const float* x = nullptr; const float* w_qkv = nullptr;
    const float* w_proj = nullptr; const float* b_proj = nullptr;
    for (int i = 0; i < n_in; i++) {
        switch (in_sizes[i]) {
            case M_ * C_:  x      = (const float*)d_in[i]; break;
            case C_ * N3_: w_qkv  = (const float*)d_in[i]; break;
            case C_ * C_:  w_proj = (const float*)d_in[i]; break;
            case C_:       b_proj = (const float*)d_in[i]; break;
        }
    }
    float* out = (float*)d_out;

    void *p_qkv, *p_ctx, *p_xh, *p_xl, *p_cxh, *p_cxl;
    void *p_wqh, *p_wql, *p_wph, *p_wpl;
    cudaGetSymbolAddress(&p_qkv, g_qkv);
    cudaGetSymbolAddress(&p_ctx, g_ctx);
    cudaGetSymbolAddress(&p_xh,  gx_hi);  cudaGetSymbolAddress(&p_xl,  gx_lo);
    cudaGetSymbolAddress(&p_cxh, gcx_hi); cudaGetSymbolAddress(&p_cxl, gcx_lo);
    cudaGetSymbolAddress(&p_wqh, gwq_hi); cudaGetSymbolAddress(&p_wql, gwq_lo);
    cudaGetSymbolAddress(&p_wph, gwp_hi); cudaGetSymbolAddress(&p_wpl, gwp_lo);

    cudaFuncSetAttribute(gemm_mma_kernel,
                         cudaFuncAttributeMaxDynamicSharedMemorySize, GEMM_SMEM);
    cudaFuncSetAttribute(attn_kernel,
                         cudaFuncAttributeMaxDynamicSharedMemorySize, ATTN_SMEM_BYTES);

    // 1) operand prep
    split_kernel<<<(M_ * C_ / 4 + 255) / 256, 256>>>(
        x, (__nv_bfloat16*)p_xh, (__nv_bfloat16*)p_xl, M_ * C_ / 4);
    transpose_split_kernel<<<dim3(N3_ / 32, C_ / 32), dim3(32, 8)>>>(
        w_qkv, (__nv_bfloat16*)p_wqh, (__nv_bfloat16*)p_wql, C_, N3_);
    transpose_split_kernel<<<dim3(C_ / 32, C_ / 32), dim3(32, 8)>>>(
        w_proj, (__nv_bfloat16*)p_wph, (__nv_bfloat16*)p_wpl, C_, C_);

    // 2) QKV GEMM on HMMA tensor cores: [8192,2048] x [6144,2048]^T
    gemm_mma_kernel<<<dim3(N3_ / 128, M_ / 128), 256, GEMM_SMEM>>>(
        (const __nv_bfloat16*)p_xh, (const __nv_bfloat16*)p_xl,
        (const __nv_bfloat16*)p_wqh, (const __nv_bfloat16*)p_wql,
        (float*)p_qkv, nullptr, N3_, C_);

    // 3) RoPE
    rope_table_kernel<<<(T_ * 64 + 255) / 256, 256>>>();
    rope_kernel<<<(BH_ * T_ * D_) / 256, 256>>>();

    // 4) causal flash attention (fp32)
    attn_kernel<<<dim3(T_ / 64, BH_), 256, ATTN_SMEM_BYTES>>>();

    // 5) projection: split ctx, then HMMA GEMM + bias -> out
    split_kernel<<<(M_ * C_ / 4 + 255) / 256, 256>>>(
        (const float*)p_ctx, (__nv_bfloat16*)p_cxh, (__nv_bfloat16*)p_cxl, M_ * C_ / 4);
    gemm_mma_kernel<<<dim3(C_ / 128, M_ / 128), 256, GEMM_SMEM>>>(
        (const __nv_bfloat16*)p_cxh, (const __nv_bfloat16*)p_cxl,
        (const __nv_bfloat16*)p_wph, (const __nv_bfloat16*)p_wpl,
        out, b_proj, C_, C_);
}

// round 4
// speedup vs baseline: 3.4068x; 1.9161x over previous
#include <cuda_runtime.h>
#include <cuda_bf16.h>
#include <math.h>
#include <stdint.h>

// Problem constants
#define B_   4
#define T_   2048
#define C_   2048
#define H_   16
#define D_   128
#define BH_  (B_ * H_)        // 64
#define M_   (B_ * T_)        // 8192
#define N3_  (3 * C_)         // 6144

// ============================ helpers ======================================
__device__ __forceinline__ uint32_t smem_u32(const void* p) {
    uint32_t a;
    asm("{ .reg .u64 t; cvta.to.shared.u64 t, %1; cvt.u32.u64 %0, t; }"
        : "=r"(a) : "l"(p));
    return a;
}
#define CP_ASYNC16(saddr, gptr) \
    asm volatile("cp.async.cg.shared.global [%0], [%1], 16;" \
                 :: "r"(saddr), "l"(gptr) : "memory")
#define CP_COMMIT() asm volatile("cp.async.commit_group;" ::: "memory")
#define CP_WAIT1()  asm volatile("cp.async.wait_group 1;" ::: "memory")

#define LDMATRIX_X4(r0, r1, r2, r3, addr) \
    asm volatile("ldmatrix.sync.aligned.m8n8.x4.shared.b16 {%0,%1,%2,%3}, [%4];" \
                 : "=r"(r0), "=r"(r1), "=r"(r2), "=r"(r3) : "r"(addr))
#define LDMATRIX_X4_T(r0, r1, r2, r3, addr) \
    asm volatile("ldmatrix.sync.aligned.m8n8.x4.trans.shared.b16 {%0,%1,%2,%3}, [%4];" \
                 : "=r"(r0), "=r"(r1), "=r"(r2), "=r"(r3) : "r"(addr))
#define LDMATRIX_X2(r0, r1, addr) \
    asm volatile("ldmatrix.sync.aligned.m8n8.x2.shared.b16 {%0,%1}, [%2];" \
                 : "=r"(r0), "=r"(r1) : "r"(addr))
#define MMA_BF16(c, a, b) \
    asm volatile("mma.sync.aligned.m16n8k16.row.col.f32.bf16.bf16.f32 " \
                 "{%0,%1,%2,%3}, {%4,%5,%6,%7}, {%8,%9}, {%0,%1,%2,%3};" \
                 : "+f"((c)[0]), "+f"((c)[1]), "+f"((c)[2]), "+f"((c)[3]) \
                 : "r"((a)[0]), "r"((a)[1]), "r"((a)[2]), "r"((a)[3]), \
                   "r"((b)[0]), "r"((b)[1]))

__device__ __forceinline__ void split2(float x, float y, uint32_t& h, uint32_t& l) {
    __nv_bfloat162 hh = __floats2bfloat162_rn(x, y);
    float hx = __low2float(hh), hy = __high2float(hh);
    __nv_bfloat162 ll = __floats2bfloat162_rn(x - hx, y - hy);
    h = *(uint32_t*)&hh; l = *(uint32_t*)&ll;
}

// ---------------- scratch (device globals; no allocation allowed) ----------
__device__ float g_qkv[M_ * N3_];          // [8192, 6144] fp32
__device__ float g_cos[T_ * 64];
__device__ float g_sin[T_ * 64];
// split-bf16 operands
__device__ __nv_bfloat16 gx_hi[M_ * C_],  gx_lo[M_ * C_];      // activations [M,K]
__device__ __nv_bfloat16 gcx_hi[M_ * C_], gcx_lo[M_ * C_];     // ctx [M,K]
__device__ __nv_bfloat16 gwq_hi[N3_ * C_], gwq_lo[N3_ * C_];   // W_qkv^T [N,K]
__device__ __nv_bfloat16 gwp_hi[C_ * C_],  gwp_lo[C_ * C_];    // W_proj^T [N,K]
// attention operands [BH, T, D] bf16 hi/lo
__device__ __nv_bfloat16 gq_hi[BH_ * T_ * D_], gq_lo[BH_ * T_ * D_];
__device__ __nv_bfloat16 gk_hi[BH_ * T_ * D_], gk_lo[BH_ * T_ * D_];
__device__ __nv_bfloat16 gv_hi[BH_ * T_ * D_], gv_lo[BH_ * T_ * D_];

// ---------------------------------------------------------------------------
// split fp32 -> (hi, lo) bf16, elementwise (vectorized by 4)
// ---------------------------------------------------------------------------
__global__ void __launch_bounds__(256) split_kernel(
    const float* __restrict__ in, __nv_bfloat16* __restrict__ hi,
    __nv_bfloat16* __restrict__ lo, int n4)
{
    int i = blockIdx.x * 256 + threadIdx.x;
    if (i >= n4) return;
    float4 v = ((const float4*)in)[i];
    __nv_bfloat16 h0 = __float2bfloat16(v.x), h1 = __float2bfloat16(v.y);
    __nv_bfloat16 h2 = __float2bfloat16(v.z), h3 = __float2bfloat16(v.w);
    __nv_bfloat16 l0 = __float2bfloat16(v.x - __bfloat162float(h0));
    __nv_bfloat16 l1 = __float2bfloat16(v.y - __bfloat162float(h1));
    __nv_bfloat16 l2 = __float2bfloat16(v.z - __bfloat162float(h2));
    __nv_bfloat16 l3 = __float2bfloat16(v.w - __bfloat162float(h3));
    __nv_bfloat162* hp = (__nv_bfloat162*)hi;
    __nv_bfloat162* lp = (__nv_bfloat162*)lo;
    hp[i * 2 + 0] = __nv_bfloat162(h0, h1);
    hp[i * 2 + 1] = __nv_bfloat162(h2, h3);
    lp[i * 2 + 0] = __nv_bfloat162(l0, l1);
    lp[i * 2 + 1] = __nv_bfloat162(l2, l3);
}

// ---------------------------------------------------------------------------
// transpose + split: W[K,N] fp32 -> Th/Tl[N,K] bf16
// ---------------------------------------------------------------------------
__global__ void __launch_bounds__(256) transpose_split_kernel(
    const float* __restrict__ W, __nv_bfloat16* __restrict__ Th,
    __nv_bfloat16* __restrict__ Tl, int K, int N)
{
    __shared__ float t[32][33];
    int bn = blockIdx.x * 32;
    int bk = blockIdx.y * 32;
    int x = threadIdx.x, y = threadIdx.y;       // 32 x 8
#pragma unroll
    for (int i = 0; i < 32; i += 8)
        t[y + i][x] = W[(size_t)(bk + y + i) * N + bn + x];
    __syncthreads();
#pragma unroll
    for (int i = 0; i < 32; i += 8) {
        float v = t[x][y + i];                  // = W[bk+x][bn+y+i]
        __nv_bfloat16 h = __float2bfloat16(v);
        __nv_bfloat16 l = __float2bfloat16(v - __bfloat162float(h));
        size_t o = (size_t)(bn + y + i) * K + bk + x;
        Th[o] = h; Tl[o] = l;
    }
}

// ---------------------------------------------------------------------------
// HMMA GEMM: C[M,N] = A[M,K] @ B[N,K]^T, split-bf16 x3 (hi*hi + hi*lo + lo*hi)
// CTA 128x128, BK=64, 2-stage cp.async, 8 warps (2x4), warp tile 64x32.
// ---------------------------------------------------------------------------
#define STG_BYTES 65536
#define OFF_AH 0
#define OFF_AL 16384
#define OFF_BH 32768
#define OFF_BL 49152
#define GEMM_SMEM (2 * STG_BYTES)

__device__ __forceinline__ void gemm_load_stage(
    uint32_t sb, int stage,
    const __nv_bfloat16* __restrict__ Ah, const __nv_bfloat16* __restrict__ Al,
    const __nv_bfloat16* __restrict__ Bh, const __nv_bfloat16* __restrict__ Bl,
    int row0, int col0, int kb, int K, int tid)
{
    uint32_t st = sb + stage * STG_BYTES;
    const int k0 = kb * 64;
#pragma unroll
    for (int u = 0; u < 4; u++) {
        int idx = u * 256 + tid;                 // 1024 16B chunks per operand
        int r = idx >> 3, c = idx & 7;
        uint32_t sw = (uint32_t)(r * 128 + ((c ^ (r & 7)) << 4));
        size_t ga = (size_t)(row0 + r) * K + k0 + c * 8;
        size_t gb = (size_t)(col0 + r) * K + k0 + c * 8;
        CP_ASYNC16(st + OFF_AH + sw, Ah + ga);
        CP_ASYNC16(st + OFF_AL + sw, Al + ga);
        CP_ASYNC16(st + OFF_BH + sw, Bh + gb);
        CP_ASYNC16(st + OFF_BL + sw, Bl + gb);
    }
}

__global__ void __launch_bounds__(256) gemm_mma_kernel(
    const __nv_bfloat16* __restrict__ Ah, const __nv_bfloat16* __restrict__ Al,
    const __nv_bfloat16* __restrict__ Bh, const __nv_bfloat16* __restrict__ Bl,
    float* __restrict__ Cout, const float* __restrict__ bias, int N, int K)
{
    extern __shared__ __align__(1024) char smem[];
    const uint32_t sb = smem_u32(smem);
    const int tid = threadIdx.x;
    const int wid = tid >> 5, lane = tid & 31;
    const int wr = wid >> 2, wc = wid & 3;       // warp grid 2 x 4
    const int col0 = blockIdx.x * 128;
    const int row0 = blockIdx.y * 128;
    const int NK = K / 64;

    float acc[4][4][4];
#pragma unroll
    for (int i = 0; i < 4; i++)
#pragma unroll
        for (int j = 0; j < 4; j++)
#pragma unroll
            for (int k = 0; k < 4; k++) acc[i][j][k] = 0.f;

    gemm_load_stage(sb, 0, Ah, Al, Bh, Bl, row0, col0, 0, K, tid);
    CP_COMMIT();
    gemm_load_stage(sb, 1, Ah, Al, Bh, Bl, row0, col0, 1, K, tid);
    CP_COMMIT();

    const int a_row = wr * 64 + (lane & 15);
    const int b_row = wc * 32 + (lane & 7);
    const int a_cg  = (lane >> 4);
    const int b_cg  = ((lane >> 3) & 1);

    for (int kb = 0; kb < NK; kb++) {
        CP_WAIT1();
        __syncthreads();
        uint32_t st = sb + (kb & 1) * STG_BYTES;

#pragma unroll
        for (int ks = 0; ks < 4; ks++) {
            uint32_t ah[4][4], alr[4][4], bh[4][2], bl[4][2];
#pragma unroll
            for (int mt = 0; mt < 4; mt++) {
                int r = a_row + mt * 16;
                int c = ks * 2 + a_cg;
                uint32_t ad = st + (uint32_t)(r * 128 + ((c ^ (r & 7)) << 4));
                LDMATRIX_X4(ah[mt][0], ah[mt][1], ah[mt][2], ah[mt][3], ad + OFF_AH);
                LDMATRIX_X4(alr[mt][0], alr[mt][1], alr[mt][2], alr[mt][3], ad + OFF_AL);
            }
#pragma unroll
            for (int nt = 0; nt < 4; nt++) {
                int n = b_row + nt * 8;
                int c = ks * 2 + b_cg;
                uint32_t bd = st + (uint32_t)(n * 128 + ((c ^ (n & 7)) << 4));
                LDMATRIX_X2(bh[nt][0], bh[nt][1], bd + OFF_BH);
                LDMATRIX_X2(bl[nt][0], bl[nt][1], bd + OFF_BL);
            }
#pragma unroll
            for (int mt = 0; mt < 4; mt++)
#pragma unroll
                for (int nt = 0; nt < 4; nt++) {
                    MMA_BF16(acc[mt][nt], ah[mt], bh[nt]);
                    MMA_BF16(acc[mt][nt], ah[mt], bl[nt]);
                    MMA_BF16(acc[mt][nt], alr[mt], bh[nt]);
                }
        }
        __syncthreads();
        if (kb + 2 < NK)
            gemm_load_stage(sb, kb & 1, Ah, Al, Bh, Bl, row0, col0, kb + 2, K, tid);
        CP_COMMIT();
    }

    const int er = lane >> 2;
    const int ec = (lane & 3) * 2;
#pragma unroll
    for (int mt = 0; mt < 4; mt++) {
        int row = row0 + wr * 64 + mt * 16 + er;
#pragma unroll
        for (int nt = 0; nt < 4; nt++) {
            int col = col0 + wc * 32 + nt * 8 + ec;
            float b0 = 0.f, b1 = 0.f;
            if (bias) { b0 = bias[col]; b1 = bias[col + 1]; }
            float2 v0, v1;
            v0.x = acc[mt][nt][0] + b0; v0.y = acc[mt][nt][1] + b1;
            v1.x = acc[mt][nt][2] + b0; v1.y = acc[mt][nt][3] + b1;
            *(float2*)&Cout[(size_t)row * N + col] = v0;
            *(float2*)&Cout[(size_t)(row + 8) * N + col] = v1;
        }
    }
}

// ---------------------------------------------------------------------------
// RoPE table
// ---------------------------------------------------------------------------
__global__ void rope_table_kernel()
{
    int g = blockIdx.x * blockDim.x + threadIdx.x;
    if (g >= T_ * 64) return;
    int t = g >> 6, i = g & 63;
    double invf = pow(10000.0, -(double)i / 64.0);
    float  angf = (float)t * (float)invf;
    double ang  = (double)angf;
    g_cos[g] = (float)cos(ang);
    g_sin[g] = (float)sin(ang);
}

// ---------------------------------------------------------------------------
// RoPE + split/transpose: g_qkv[B,T,3C] -> q/k/v hi/lo bf16 [BH,T,D]
// ---------------------------------------------------------------------------
__global__ void __launch_bounds__(256) rope_kernel()
{
    int g = blockIdx.x * 256 + threadIdx.x;
    int d  = g & 127;
    int t  = (g >> 7) & 2047;
    int bh = g >> 18;
    int b  = bh >> 4, h = bh & 15;

    size_t src = ((size_t)(b * T_ + t)) * N3_ + h * D_ + d;
    int dp = (d + 64) & 127;
    size_t srcp = src - d + dp;

    float qa = g_qkv[src];
    float ka = g_qkv[src + C_];
    float va = g_qkv[src + 2 * C_];
    float qb = g_qkv[srcp];
    float kb = g_qkv[srcp + C_];

    float sgn = (d < 64) ? -1.f : 1.f;
    int i = d & 63;
    float c = g_cos[t * 64 + i];
    float s = g_sin[t * 64 + i];

    float qr = qa * c + sgn * qb * s;
    float kr = ka * c + sgn * kb * s;

    size_t dst = ((size_t)bh * T_ + t) * D_ + d;
    __nv_bfloat16 qh = __float2bfloat16(qr);
    gq_hi[dst] = qh; gq_lo[dst] = __float2bfloat16(qr - __bfloat162float(qh));
    __nv_bfloat16 kh = __float2bfloat16(kr);
    gk_hi[dst] = kh; gk_lo[dst] = __float2bfloat16(kr - __bfloat162float(kh));
    __nv_bfloat16 vh = __float2bfloat16(va);
    gv_hi[dst] = vh; gv_lo[dst] = __float2bfloat16(va - __bfloat162float(vh));
}

// ---------------------------------------------------------------------------
// Flash attention (causal) on HMMA, split-bf16 x3 for both QK and PV.
// CTA = (128 q rows, one bh); 8 warps of 16 rows; K-tiles of 64 keys;
// 2-stage cp.async. Smem: Q 64KB + 2 x 64KB KV stages = 192KB.
// Writes ctx hi/lo bf16 directly.
// ---------------------------------------------------------------------------
#define ATTN_SMEM 196608

__device__ __forceinline__ void attn_load_kv(
    uint32_t skv, int stage,
    const __nv_bfloat16* __restrict__ kh, const __nv_bfloat16* __restrict__ kl,
    const __nv_bfloat16* __restrict__ vh, const __nv_bfloat16* __restrict__ vl,
    int k0, int tid)
{
    uint32_t st = skv + stage * 65536;
    const __nv_bfloat16* srcs[4] = {kh, kl, vh, vl};
#pragma unroll
    for (int u = 0; u < 16; u++) {
        int idx = u * 256 + tid;
        int a = u >> 2;                     // constant per unrolled u
        int rem = idx & 1023;
        int r = rem >> 4, c = rem & 15;
        uint32_t dst = st + a * 16384 + r * 256 + ((c ^ (r & 7)) << 4);
        CP_ASYNC16(dst, srcs[a] + (size_t)(k0 + r) * D_ + c * 8);
    }
}

__global__ void __launch_bounds__(256, 1) attn_mma_kernel()
{
    extern __shared__ __align__(1024) char smem[];
    const uint32_t sb = smem_u32(smem);
    const int tid = threadIdx.x;
    const int w = tid >> 5, lane = tid & 31;
    const int g = lane >> 2, tig = lane & 3;
    const int qt = (int)gridDim.x - 1 - (int)blockIdx.x;   // heavy tiles first
    const int bh = blockIdx.y;
    const int q0 = qt * 128;
    const int NT = 2 * (qt + 1);

    const size_t hb = (size_t)bh * T_ * D_;
    const __nv_bfloat16* Qh = gq_hi + hb;
    const __nv_bfloat16* Ql = gq_lo + hb;
    const __nv_bfloat16* Kh = gk_hi + hb;
    const __nv_bfloat16* Kl = gk_lo + hb;
    const __nv_bfloat16* Vh = gv_hi + hb;
    const __nv_bfloat16* Vl = gv_lo + hb;

    const uint32_t sq = sb;
    const uint32_t skv = sb + 65536;

    // Load Q tile (hi/lo), rows 256B swizzled
#pragma unroll
    for (int u = 0; u < 16; u++) {
        int idx = u * 256 + tid;
        int a = u >> 3;                    // 0: hi, 1: lo
        int rem = idx & 2047;
        int r = rem >> 4, c = rem & 15;
        uint32_t dst = sq + a * 32768 + r * 256 + ((c ^ (r & 7)) << 4);
        const __nv_bfloat16* src = (a == 0 ? Qh : Ql) + (size_t)(q0 + r) * D_ + c * 8;
        CP_ASYNC16(dst, src);
    }
    attn_load_kv(skv, 0, Kh, Kl, Vh, Vl, 0, tid);
    CP_COMMIT();
    if (NT > 1) attn_load_kv(skv, 1, Kh, Kl, Vh, Vl, 64, tid);
    CP_COMMIT();

    float O[16][4];
#pragma unroll
    for (int i = 0; i < 16; i++)
#pragma unroll
        for (int j = 0; j < 4; j++) O[i][j] = 0.f;
    float m0 = -1e30f, m1 = -1e30f, l0 = 0.f, l1 = 0.f;
    const float scale = 0.08838834764831845f;
    const int row0 = q0 + w * 16 + g;
    const int row1 = row0 + 8;

    for (int kt = 0; kt < NT; kt++) {
        CP_WAIT1();
        __syncthreads();
        const uint32_t sk = skv + (kt & 1) * 65536;

        // S = Q K^T (split x3)
        float S[8][4];
#pragma unroll
        for (int i = 0; i < 8; i++)
#pragma unroll
            for (int j = 0; j < 4; j++) S[i][j] = 0.f;

#pragma unroll
        for (int ks = 0; ks < 8; ks++) {
            int qrow = w * 16 + (lane & 15);
            int qc = 2 * ks + (lane >> 4);
            uint32_t qa = sq + qrow * 256 + ((qc ^ (qrow & 7)) << 4);
            uint32_t ah[4], al[4];
            LDMATRIX_X4(ah[0], ah[1], ah[2], ah[3], qa);
            LDMATRIX_X4(al[0], al[1], al[2], al[3], qa + 32768);
#pragma unroll
            for (int np = 0; np < 4; np++) {
                int kr = np * 16 + (lane & 7) + ((lane >> 4) << 3);
                int kc = 2 * ks + ((lane >> 3) & 1);
                uint32_t ka = sk + kr * 256 + ((kc ^ (kr & 7)) << 4);
                uint32_t bh4[4], bl4[4];
                LDMATRIX_X4(bh4[0], bh4[1], bh4[2], bh4[3], ka);
                LDMATRIX_X4(bl4[0], bl4[1], bl4[2], bl4[3], ka + 16384);
                MMA_BF16(S[2 * np],     ah, bh4);
                MMA_BF16(S[2 * np],     ah, bl4);
                MMA_BF16(S[2 * np],     al, bh4);
                MMA_BF16(S[2 * np + 1], ah, bh4 + 2);
                MMA_BF16(S[2 * np + 1], ah, bl4 + 2);
                MMA_BF16(S[2 * np + 1], al, bh4 + 2);
            }
        }

        // scale + causal mask (diagonal region only)
        const bool dom = (kt >= 2 * qt);
#pragma unroll
        for (int nt = 0; nt < 8; nt++)
#pragma unroll
            for (int q = 0; q < 4; q++) {
                float v = S[nt][q] * scale;
                if (dom) {
                    int col = kt * 64 + nt * 8 + 2 * tig + (q & 1);
                    int row = (q < 2) ? row0 : row1;
                    if (col > row) v = -1e30f;
                }
                S[nt][q] = v;
            }

        // online softmax
        float mx0 = -1e30f, mx1 = -1e30f;
#pragma unroll
        for (int nt = 0; nt < 8; nt++) {
            mx0 = fmaxf(mx0, fmaxf(S[nt][0], S[nt][1]));
            mx1 = fmaxf(mx1, fmaxf(S[nt][2], S[nt][3]));
        }
        mx0 = fmaxf(mx0, __shfl_xor_sync(0xffffffffu, mx0, 1));
        mx0 = fmaxf(mx0, __shfl_xor_sync(0xffffffffu, mx0, 2));
        mx1 = fmaxf(mx1, __shfl_xor_sync(0xffffffffu, mx1, 1));
        mx1 = fmaxf(mx1, __shfl_xor_sync(0xffffffffu, mx1, 2));
        float mn0 = fmaxf(m0, mx0), mn1 = fmaxf(m1, mx1);
        float a0 = __expf(m0 - mn0), a1 = __expf(m1 - mn1);
        m0 = mn0; m1 = mn1;
        float s0 = 0.f, s1 = 0.f;
#pragma unroll
        for (int nt = 0; nt < 8; nt++) {
            S[nt][0] = __expf(S[nt][0] - mn0); s0 += S[nt][0];
            S[nt][1] = __expf(S[nt][1] - mn0); s0 += S[nt][1];
            S[nt][2] = __expf(S[nt][2] - mn1); s1 += S[nt][2];
            S[nt][3] = __expf(S[nt][3] - mn1); s1 += S[nt][3];
        }
        s0 += __shfl_xor_sync(0xffffffffu, s0, 1);
        s0 += __shfl_xor_sync(0xffffffffu, s0, 2);
        s1 += __shfl_xor_sync(0xffffffffu, s1, 1);
        s1 += __shfl_xor_sync(0xffffffffu, s1, 2);
        l0 = l0 * a0 + s0;
        l1 = l1 * a1 + s1;
#pragma unroll
        for (int nt = 0; nt < 16; nt++) {
            O[nt][0] *= a0; O[nt][1] *= a0;
            O[nt][2] *= a1; O[nt][3] *= a1;
        }

        // O += P V (split x3); P fragments come straight from S accumulators
#pragma unroll
        for (int j = 0; j < 4; j++) {
            uint32_t ph[4], pl[4];
            split2(S[2 * j][0],     S[2 * j][1],     ph[0], pl[0]);
            split2(S[2 * j][2],     S[2 * j][3],     ph[1], pl[1]);
            split2(S[2 * j + 1][0], S[2 * j + 1][1], ph[2], pl[2]);
            split2(S[2 * j + 1][2], S[2 * j + 1][3], ph[3], pl[3]);
#pragma unroll
            for (int np = 0; np < 8; np++) {
                int vr = j * 16 + (lane & 15);
                int vc = 2 * np + (lane >> 4);
                uint32_t va = sk + 32768 + vr * 256 + ((vc ^ (vr & 7)) << 4);
                uint32_t vh4[4], vl4[4];
                LDMATRIX_X4_T(vh4[0], vh4[1], vh4[2], vh4[3], va);
                LDMATRIX_X4_T(vl4[0], vl4[1], vl4[2], vl4[3], va + 16384);
                MMA_BF16(O[2 * np],     ph, vh4);
                MMA_BF16(O[2 * np],     ph, vl4);
                MMA_BF16(O[2 * np],     pl, vh4);
                MMA_BF16(O[2 * np + 1], ph, vh4 + 2);
                MMA_BF16(O[2 * np + 1], ph, vl4 + 2);
                MMA_BF16(O[2 * np + 1], pl, vh4 + 2);
            }
        }
        __syncthreads();
        if (kt + 2 < NT)
            attn_load_kv(skv, kt & 1, Kh, Kl, Vh, Vl, (kt + 2) * 64, tid);
        CP_COMMIT();
    }

    // Epilogue: normalize, stage to smem, write ctx hi/lo bf16
    float li0 = 1.0f / l0, li1 = 1.0f / l1;
    float* stg = (float*)smem;
    {
        int r0l = w * 16 + g, r1l = r0l + 8;
#pragma unroll
        for (int nt = 0; nt < 16; nt++) {
            float2 v0 = make_float2(O[nt][0] * li0, O[nt][1] * li0);
            float2 v1 = make_float2(O[nt][2] * li1, O[nt][3] * li1);
            *(float2*)&stg[r0l * 132 + nt * 8 + 2 * tig] = v0;
            *(float2*)&stg[r1l * 132 + nt * 8 + 2 * tig] = v1;
        }
    }
    __syncthreads();
    {
        int r = tid >> 1, ch = (tid & 1) * 64;
        int b = bh >> 4, h = bh & 15;
        size_t base = ((size_t)(b * T_ + q0 + r)) * C_ + h * 128 + ch;
#pragma unroll
        for (int c = 0; c < 64; c += 2) {
            float x = stg[r * 132 + ch + c], y = stg[r * 132 + ch + c + 1];
            __nv_bfloat162 hh = __floats2bfloat162_rn(x, y);
            float hx = __low2float(hh), hy = __high2float(hh);
            __nv_bfloat162 ll = __floats2bfloat162_rn(x - hx, y - hy);
            *(__nv_bfloat162*)&gcx_hi[base + c] = hh;
            *(__nv_bfloat162*)&gcx_lo[base + c] = ll;
        }
    }
}

// ---------------------------------------------------------------------------
extern "C" void kernel_launch(void* const* d_in, const int* in_sizes, int n_in,
                              void* d_out, int out_size)
{
    const float* x = nullptr; const float* w_qkv = nullptr;
    const float* w_proj = nullptr; const float* b_proj = nullptr;
    for (int i = 0; i < n_in; i++) {
        switch (in_sizes[i]) {
            case M_ * C_:  x      = (const float*)d_in[i]; break;
            case C_ * N3_: w_qkv  = (const float*)d_in[i]; break;
            case C_ * C_:  w_proj = (const float*)d_in[i]; break;
            case C_:       b_proj = (const float*)d_in[i]; break;
        }
    }
    float* out = (float*)d_out;

    void *p_qkv, *p_xh, *p_xl, *p_cxh, *p_cxl;
    void *p_wqh, *p_wql, *p_wph, *p_wpl;
    cudaGetSymbolAddress(&p_qkv, g_qkv);
    cudaGetSymbolAddress(&p_xh,  gx_hi);  cudaGetSymbolAddress(&p_xl,  gx_lo);
    cudaGetSymbolAddress(&p_cxh, gcx_hi); cudaGetSymbolAddress(&p_cxl, gcx_lo);
    cudaGetSymbolAddress(&p_wqh, gwq_hi); cudaGetSymbolAddress(&p_wql, gwq_lo);
    cudaGetSymbolAddress(&p_wph, gwp_hi); cudaGetSymbolAddress(&p_wpl, gwp_lo);

    cudaFuncSetAttribute(gemm_mma_kernel,
                         cudaFuncAttributeMaxDynamicSharedMemorySize, GEMM_SMEM);
    cudaFuncSetAttribute(attn_mma_kernel,
                         cudaFuncAttributeMaxDynamicSharedMemorySize, ATTN_SMEM);

    // 1) operand prep
    split_kernel<<<(M_ * C_ / 4 + 255) / 256, 256>>>(
        x, (__nv_bfloat16*)p_xh, (__nv_bfloat16*)p_xl, M_ * C_ / 4);
    transpose_split_kernel<<<dim3(N3_ / 32, C_ / 32), dim3(32, 8)>>>(
        w_qkv, (__nv_bfloat16*)p_wqh, (__nv_bfloat16*)p_wql, C_, N3_);
    transpose_split_kernel<<<dim3(C_ / 32, C_ / 32), dim3(32, 8)>>>(
        w_proj, (__nv_bfloat16*)p_wph, (__nv_bfloat16*)p_wpl, C_, C_);

    // 2) QKV GEMM (HMMA): [8192,2048] x [6144,2048]^T
    gemm_mma_kernel<<<dim3(N3_ / 128, M_ / 128), 256, GEMM_SMEM>>>(
        (const __nv_bfloat16*)p_xh, (const __nv_bfloat16*)p_xl,
        (const __nv_bfloat16*)p_wqh, (const __nv_bfloat16*)p_wql,
        (float*)p_qkv, nullptr, N3_, C_);

    // 3) RoPE -> bf16 hi/lo q/k/v
    rope_table_kernel<<<(T_ * 64 + 255) / 256, 256>>>();
    rope_kernel<<<(BH_ * T_ * D_) / 256, 256>>>();

    // 4) causal flash attention on HMMA (writes ctx hi/lo directly)
    attn_mma_kernel<<<dim3(T_ / 128, BH_), 256, ATTN_SMEM>>>();

    // 5) projection GEMM (HMMA) + bias -> out
    gemm_mma_kernel<<<dim3(C_ / 128, M_ / 128), 256, GEMM_SMEM>>>(
        (const __nv_bfloat16*)p_cxh, (const __nv_bfloat16*)p_cxl,
        (const __nv_bfloat16*)p_wph, (const __nv_bfloat16*)p_wpl,
        out, b_proj, C_, C_);
}

// round 5
// speedup vs baseline: 3.5300x; 1.0361x over previous
#include <cuda_runtime.h>
#include <cuda_bf16.h>
#include <cuda_fp16.h>
#include <math.h>
#include <stdint.h>

// Problem constants
#define B_   4
#define T_   2048
#define C_   2048
#define H_   16
#define D_   128
#define BH_  (B_ * H_)        // 64
#define M_   (B_ * T_)        // 8192
#define N3_  (3 * C_)         // 6144

// ============================ helpers ======================================
__device__ __forceinline__ uint32_t smem_u32(const void* p) {
    uint32_t a;
    asm("{ .reg .u64 t; cvta.to.shared.u64 t, %1; cvt.u32.u64 %0, t; }"
        : "=r"(a) : "l"(p));
    return a;
}
#define CP_ASYNC16(saddr, gptr) \
    asm volatile("cp.async.cg.shared.global [%0], [%1], 16;" \
                 :: "r"(saddr), "l"(gptr) : "memory")
#define CP_COMMIT() asm volatile("cp.async.commit_group;" ::: "memory")
#define CP_WAIT_GROUP(n) asm volatile("cp.async.wait_group %0;" :: "n"(n) : "memory")

#define LDMATRIX_X4(r0, r1, r2, r3, addr) \
    asm volatile("ldmatrix.sync.aligned.m8n8.x4.shared.b16 {%0,%1,%2,%3}, [%4];" \
                 : "=r"(r0), "=r"(r1), "=r"(r2), "=r"(r3) : "r"(addr))
#define LDMATRIX_X4_T(r0, r1, r2, r3, addr) \
    asm volatile("ldmatrix.sync.aligned.m8n8.x4.trans.shared.b16 {%0,%1,%2,%3}, [%4];" \
                 : "=r"(r0), "=r"(r1), "=r"(r2), "=r"(r3) : "r"(addr))
#define LDMATRIX_X2(r0, r1, addr) \
    asm volatile("ldmatrix.sync.aligned.m8n8.x2.shared.b16 {%0,%1}, [%2];" \
                 : "=r"(r0), "=r"(r1) : "r"(addr))
#define MMA_BF16(c, a, b) \
    asm volatile("mma.sync.aligned.m16n8k16.row.col.f32.bf16.bf16.f32 " \
                 "{%0,%1,%2,%3}, {%4,%5,%6,%7}, {%8,%9}, {%0,%1,%2,%3};" \
                 : "+f"((c)[0]), "+f"((c)[1]), "+f"((c)[2]), "+f"((c)[3]) \
                 : "r"((a)[0]), "r"((a)[1]), "r"((a)[2]), "r"((a)[3]), \
                   "r"((b)[0]), "r"((b)[1]))
#define MMA_FP16(c, a, b) \
    asm volatile("mma.sync.aligned.m16n8k16.row.col.f32.f16.f16.f32 " \
                 "{%0,%1,%2,%3}, {%4,%5,%6,%7}, {%8,%9}, {%0,%1,%2,%3};" \
                 : "+f"((c)[0]), "+f"((c)[1]), "+f"((c)[2]), "+f"((c)[3]) \
                 : "r"((a)[0]), "r"((a)[1]), "r"((a)[2]), "r"((a)[3]), \
                   "r"((b)[0]), "r"((b)[1]))

// ---------------- scratch (device globals; no allocation allowed) ----------
__device__ float g_qkv[M_ * N3_];          // [8192, 6144] fp32
__device__ float g_cos[T_ * 64];
__device__ float g_sin[T_ * 64];
// split-bf16 operands
__device__ __nv_bfloat16 gx_hi[M_ * C_],  gx_lo[M_ * C_];      // activations [M,K]
__device__ __nv_bfloat16 gcx_hi[M_ * C_], gcx_lo[M_ * C_];     // ctx [M,K]
__device__ __nv_bfloat16 gwq_hi[N3_ * C_], gwq_lo[N3_ * C_];   // W_qkv^T [N,K]
__device__ __nv_bfloat16 gwp_hi[C_ * C_],  gwp_lo[C_ * C_];    // W_proj^T [N,K]
// attention operands [BH, T, D]: q/k bf16 hi/lo, v fp16 hi/lo
__device__ __nv_bfloat16 gq_hi[BH_ * T_ * D_], gq_lo[BH_ * T_ * D_];
__device__ __nv_bfloat16 gk_hi[BH_ * T_ * D_], gk_lo[BH_ * T_ * D_];
__device__ __half        gv_hi[BH_ * T_ * D_], gv_lo[BH_ * T_ * D_];

// ---------------------------------------------------------------------------
// split fp32 -> (hi, lo) bf16, elementwise (vectorized by 4)
// ---------------------------------------------------------------------------
__global__ void __launch_bounds__(256) split_kernel(
    const float* __restrict__ in, __nv_bfloat16* __restrict__ hi,
    __nv_bfloat16* __restrict__ lo, int n4)
{
    int i = blockIdx.x * 256 + threadIdx.x;
    if (i >= n4) return;
    float4 v = ((const float4*)in)[i];
    __nv_bfloat16 h0 = __float2bfloat16(v.x), h1 = __float2bfloat16(v.y);
    __nv_bfloat16 h2 = __float2bfloat16(v.z), h3 = __float2bfloat16(v.w);
    __nv_bfloat16 l0 = __float2bfloat16(v.x - __bfloat162float(h0));
    __nv_bfloat16 l1 = __float2bfloat16(v.y - __bfloat162float(h1));
    __nv_bfloat16 l2 = __float2bfloat16(v.z - __bfloat162float(h2));
    __nv_bfloat16 l3 = __float2bfloat16(v.w - __bfloat162float(h3));
    __nv_bfloat162* hp = (__nv_bfloat162*)hi;
    __nv_bfloat162* lp = (__nv_bfloat162*)lo;
    hp[i * 2 + 0] = __nv_bfloat162(h0, h1);
    hp[i * 2 + 1] = __nv_bfloat162(h2, h3);
    lp[i * 2 + 0] = __nv_bfloat162(l0, l1);
    lp[i * 2 + 1] = __nv_bfloat162(l2, l3);
}

// ---------------------------------------------------------------------------
// transpose + split: W[K,N] fp32 -> Th/Tl[N,K] bf16
// ---------------------------------------------------------------------------
__global__ void __launch_bounds__(256) transpose_split_kernel(
    const float* __restrict__ W, __nv_bfloat16* __restrict__ Th,
    __nv_bfloat16* __restrict__ Tl, int K, int N)
{
    __shared__ float t[32][33];
    int bn = blockIdx.x * 32;
    int bk = blockIdx.y * 32;
    int x = threadIdx.x, y = threadIdx.y;       // 32 x 8
#pragma unroll
    for (int i = 0; i < 32; i += 8)
        t[y + i][x] = W[(size_t)(bk + y + i) * N + bn + x];
    __syncthreads();
#pragma unroll
    for (int i = 0; i < 32; i += 8) {
        float v = t[x][y + i];                  // = W[bk+x][bn+y+i]
        __nv_bfloat16 h = __float2bfloat16(v);
        __nv_bfloat16 l = __float2bfloat16(v - __bfloat162float(h));
        size_t o = (size_t)(bn + y + i) * K + bk + x;
        Th[o] = h; Tl[o] = l;
    }
}

// ---------------------------------------------------------------------------
// HMMA GEMM: C[M,N] = A[M,K] @ B[N,K]^T, split-bf16 x3 (hi*hi + hi*lo + lo*hi)
// CTA 128x128, BK=64, 3-stage cp.async (1 sync/iter), 8 warps (2x4).
// ---------------------------------------------------------------------------
#define STG_BYTES 65536
#define OFF_AH 0
#define OFF_AL 16384
#define OFF_BH 32768
#define OFF_BL 49152
#define GEMM_SMEM (3 * STG_BYTES)

__device__ __forceinline__ void gemm_load_stage(
    uint32_t sb, int stage,
    const __nv_bfloat16* __restrict__ Ah, const __nv_bfloat16* __restrict__ Al,
    const __nv_bfloat16* __restrict__ Bh, const __nv_bfloat16* __restrict__ Bl,
    int row0, int col0, int kb, int K, int tid)
{
    uint32_t st = sb + stage * STG_BYTES;
    const int k0 = kb * 64;
#pragma unroll
    for (int u = 0; u < 4; u++) {
        int idx = u * 256 + tid;                 // 1024 16B chunks per operand
        int r = idx >> 3, c = idx & 7;
        uint32_t sw = (uint32_t)(r * 128 + ((c ^ (r & 7)) << 4));
        size_t ga = (size_t)(row0 + r) * K + k0 + c * 8;
        size_t gb = (size_t)(col0 + r) * K + k0 + c * 8;
        CP_ASYNC16(st + OFF_AH + sw, Ah + ga);
        CP_ASYNC16(st + OFF_AL + sw, Al + ga);
        CP_ASYNC16(st + OFF_BH + sw, Bh + gb);
        CP_ASYNC16(st + OFF_BL + sw, Bl + gb);
    }
}

__global__ void __launch_bounds__(256) gemm_mma_kernel(
    const __nv_bfloat16* __restrict__ Ah, const __nv_bfloat16* __restrict__ Al,
    const __nv_bfloat16* __restrict__ Bh, const __nv_bfloat16* __restrict__ Bl,
    float* __restrict__ Cout, const float* __restrict__ bias, int N, int K)
{
    extern __shared__ __align__(1024) char smem[];
    const uint32_t sb = smem_u32(smem);
    const int tid = threadIdx.x;
    const int wid = tid >> 5, lane = tid & 31;
    const int wr = wid >> 2, wc = wid & 3;       // warp grid 2 x 4
    const int col0 = blockIdx.x * 128;
    const int row0 = blockIdx.y * 128;
    const int NK = K / 64;

    float acc[4][4][4];
#pragma unroll
    for (int i = 0; i < 4; i++)
#pragma unroll
        for (int j = 0; j < 4; j++)
#pragma unroll
            for (int k = 0; k < 4; k++) acc[i][j][k] = 0.f;

    gemm_load_stage(sb, 0, Ah, Al, Bh, Bl, row0, col0, 0, K, tid);
    CP_COMMIT();
    gemm_load_stage(sb, 1, Ah, Al, Bh, Bl, row0, col0, 1, K, tid);
    CP_COMMIT();

    const int a_row = wr * 64 + (lane & 15);
    const int b_row = wc * 32 + (lane & 7);
    const int a_cg  = (lane >> 4);
    const int b_cg  = ((lane >> 3) & 1);

    int slot = 0;        // kb % 3
    int nslot = 2;       // (kb+2) % 3
    for (int kb = 0; kb < NK; kb++) {
        CP_WAIT_GROUP(1);
        __syncthreads();
        // issue loads for kb+2 into its slot (consumed at kb-1; sync above covers)
        if (kb + 2 < NK)
            gemm_load_stage(sb, nslot, Ah, Al, Bh, Bl, row0, col0, kb + 2, K, tid);
        CP_COMMIT();

        uint32_t st = sb + slot * STG_BYTES;
#pragma unroll
        for (int ks = 0; ks < 4; ks++) {
            uint32_t ah[4][4], alr[4][4], bh[4][2], bl[4][2];
#pragma unroll
            for (int mt = 0; mt < 4; mt++) {
                int r = a_row + mt * 16;
                int c = ks * 2 + a_cg;
                uint32_t ad = st + (uint32_t)(r * 128 + ((c ^ (r & 7)) << 4));
                LDMATRIX_X4(ah[mt][0], ah[mt][1], ah[mt][2], ah[mt][3], ad + OFF_AH);
                LDMATRIX_X4(alr[mt][0], alr[mt][1], alr[mt][2], alr[mt][3], ad + OFF_AL);
            }
#pragma unroll
            for (int nt = 0; nt < 4; nt++) {
                int n = b_row + nt * 8;
                int c = ks * 2 + b_cg;
                uint32_t bd = st + (uint32_t)(n * 128 + ((c ^ (n & 7)) << 4));
                LDMATRIX_X2(bh[nt][0], bh[nt][1], bd + OFF_BH);
                LDMATRIX_X2(bl[nt][0], bl[nt][1], bd + OFF_BL);
            }
#pragma unroll
            for (int mt = 0; mt < 4; mt++)
#pragma unroll
                for (int nt = 0; nt < 4; nt++) {
                    MMA_BF16(acc[mt][nt], ah[mt], bh[nt]);
                    MMA_BF16(acc[mt][nt], ah[mt], bl[nt]);
                    MMA_BF16(acc[mt][nt], alr[mt], bh[nt]);
                }
        }
        slot = (slot == 2) ? 0 : slot + 1;
        nslot = (nslot == 2) ? 0 : nslot + 1;
    }

    const int er = lane >> 2;
    const int ec = (lane & 3) * 2;
#pragma unroll
    for (int mt = 0; mt < 4; mt++) {
        int row = row0 + wr * 64 + mt * 16 + er;
#pragma unroll
        for (int nt = 0; nt < 4; nt++) {
            int col = col0 + wc * 32 + nt * 8 + ec;
            float b0 = 0.f, b1 = 0.f;
            if (bias) { b0 = bias[col]; b1 = bias[col + 1]; }
            float2 v0, v1;
            v0.x = acc[mt][nt][0] + b0; v0.y = acc[mt][nt][1] + b1;
            v1.x = acc[mt][nt][2] + b0; v1.y = acc[mt][nt][3] + b1;
            *(float2*)&Cout[(size_t)row * N + col] = v0;
            *(float2*)&Cout[(size_t)(row + 8) * N + col] = v1;
        }
    }
}

// ---------------------------------------------------------------------------
// RoPE table
// ---------------------------------------------------------------------------
__global__ void rope_table_kernel()
{
    int g = blockIdx.x * blockDim.x + threadIdx.x;
    if (g >= T_ * 64) return;
    int t = g >> 6, i = g & 63;
    double invf = pow(10000.0, -(double)i / 64.0);
    float  angf = (float)t * (float)invf;
    double ang  = (double)angf;
    g_cos[g] = (float)cos(ang);
    g_sin[g] = (float)sin(ang);
}

// ---------------------------------------------------------------------------
// RoPE + split/transpose: g_qkv[B,T,3C] -> q/k bf16 hi/lo, v fp16 hi/lo
// ---------------------------------------------------------------------------
__global__ void __launch_bounds__(256) rope_kernel()
{
    int g = blockIdx.x * 256 + threadIdx.x;
    int d  = g & 127;
    int t  = (g >> 7) & 2047;
    int bh = g >> 18;
    int b  = bh >> 4, h = bh & 15;

    size_t src = ((size_t)(b * T_ + t)) * N3_ + h * D_ + d;
    int dp = (d + 64) & 127;
    size_t srcp = src - d + dp;

    float qa = g_qkv[src];
    float ka = g_qkv[src + C_];
    float va = g_qkv[src + 2 * C_];
    float qb = g_qkv[srcp];
    float kb = g_qkv[srcp + C_];

    float sgn = (d < 64) ? -1.f : 1.f;
    int i = d & 63;
    float c = g_cos[t * 64 + i];
    float s = g_sin[t * 64 + i];

    float qr = qa * c + sgn * qb * s;
    float kr = ka * c + sgn * kb * s;

    size_t dst = ((size_t)bh * T_ + t) * D_ + d;
    __nv_bfloat16 qh = __float2bfloat16(qr);
    gq_hi[dst] = qh; gq_lo[dst] = __float2bfloat16(qr - __bfloat162float(qh));
    __nv_bfloat16 kh = __float2bfloat16(kr);
    gk_hi[dst] = kh; gk_lo[dst] = __float2bfloat16(kr - __bfloat162float(kh));
    __half vh = __float2half_rn(va);
    gv_hi[dst] = vh; gv_lo[dst] = __float2half_rn(va - __half2float(vh));
}

// ---------------------------------------------------------------------------
// Flash attention (causal) on HMMA.
// QK: split-bf16 x3.  PV: P fp16 (single) x V fp16 hi/lo = 2 MMAs (exact V).
// CTA = (128 q rows, one bh); 8 warps of 16 rows; K-tiles of 64 keys;
// 2-stage cp.async, 1 sync per iteration (loads issued at top).
// Writes ctx hi/lo bf16 directly.
// ---------------------------------------------------------------------------
#define ATTN_SMEM 196608

__device__ __forceinline__ void attn_load_kv(
    uint32_t skv, int stage,
    const __nv_bfloat16* __restrict__ kh, const __nv_bfloat16* __restrict__ kl,
    const __half* __restrict__ vh, const __half* __restrict__ vl,
    int k0, int tid)
{
    uint32_t st = skv + stage * 65536;
    const void* srcs[4] = {kh, kl, vh, vl};
#pragma unroll
    for (int u = 0; u < 16; u++) {
        int idx = u * 256 + tid;
        int a = u >> 2;                     // constant per unrolled u
        int rem = idx & 1023;
        int r = rem >> 4, c = rem & 15;
        uint32_t dst = st + a * 16384 + r * 256 + ((c ^ (r & 7)) << 4);
        CP_ASYNC16(dst, (const __nv_bfloat16*)srcs[a] + (size_t)(k0 + r) * D_ + c * 8);
    }
}

__global__ void __launch_bounds__(256, 1) attn_mma_kernel()
{
    extern __shared__ __align__(1024) char smem[];
    const uint32_t sb = smem_u32(smem);
    const int tid = threadIdx.x;
    const int w = tid >> 5, lane = tid & 31;
    const int g = lane >> 2, tig = lane & 3;
    const int qt = (int)gridDim.x - 1 - (int)blockIdx.x;   // heavy tiles first
    const int bh = blockIdx.y;
    const int q0 = qt * 128;
    const int NT = 2 * (qt + 1);

    const size_t hb = (size_t)bh * T_ * D_;
    const __nv_bfloat16* Qh = gq_hi + hb;
    const __nv_bfloat16* Ql = gq_lo + hb;
    const __nv_bfloat16* Kh = gk_hi + hb;
    const __nv_bfloat16* Kl = gk_lo + hb;
    const __half* Vh = gv_hi + hb;
    const __half* Vl = gv_lo + hb;

    const uint32_t sq = sb;
    const uint32_t skv = sb + 65536;

    // Load Q tile (hi/lo), rows 256B swizzled; + KV stage 0 — one group
#pragma unroll
    for (int u = 0; u < 16; u++) {
        int idx = u * 256 + tid;
        int a = u >> 3;                    // 0: hi, 1: lo
        int rem = idx & 2047;
        int r = rem >> 4, c = rem & 15;
        uint32_t dst = sq + a * 32768 + r * 256 + ((c ^ (r & 7)) << 4);
        const __nv_bfloat16* src = (a == 0 ? Qh : Ql) + (size_t)(q0 + r) * D_ + c * 8;
        CP_ASYNC16(dst, src);
    }
    attn_load_kv(skv, 0, Kh, Kl, Vh, Vl, 0, tid);
    CP_COMMIT();

    float O[16][4];
#pragma unroll
    for (int i = 0; i < 16; i++)
#pragma unroll
        for (int j = 0; j < 4; j++) O[i][j] = 0.f;
    float m0 = -1e30f, m1 = -1e30f, l0 = 0.f, l1 = 0.f;
    const float scale = 0.08838834764831845f;
    const int row0 = q0 + w * 16 + g;
    const int row1 = row0 + 8;

    for (int kt = 0; kt < NT; kt++) {
        CP_WAIT_GROUP(0);
        __syncthreads();
        // issue next tile's loads (target slot consumed at kt-1; sync covers)
        if (kt + 1 < NT)
            attn_load_kv(skv, (kt + 1) & 1, Kh, Kl, Vh, Vl, (kt + 1) * 64, tid);
        CP_COMMIT();
        const uint32_t sk = skv + (kt & 1) * 65536;

        // S = Q K^T (split x3)
        float S[8][4];
#pragma unroll
        for (int i = 0; i < 8; i++)
#pragma unroll
            for (int j = 0; j < 4; j++) S[i][j] = 0.f;

#pragma unroll
        for (int ks = 0; ks < 8; ks++) {
            int qrow = w * 16 + (lane & 15);
            int qc = 2 * ks + (lane >> 4);
            uint32_t qa = sq + qrow * 256 + ((qc ^ (qrow & 7)) << 4);
            uint32_t ah[4], al[4];
            LDMATRIX_X4(ah[0], ah[1], ah[2], ah[3], qa);
            LDMATRIX_X4(al[0], al[1], al[2], al[3], qa + 32768);
#pragma unroll
            for (int np = 0; np < 4; np++) {
                int kr = np * 16 + (lane & 7) + ((lane >> 4) << 3);
                int kc = 2 * ks + ((lane >> 3) & 1);
                uint32_t ka = sk + kr * 256 + ((kc ^ (kr & 7)) << 4);
                uint32_t bh4[4], bl4[4];
                LDMATRIX_X4(bh4[0], bh4[1], bh4[2], bh4[3], ka);
                LDMATRIX_X4(bl4[0], bl4[1], bl4[2], bl4[3], ka + 16384);
                MMA_BF16(S[2 * np],     ah, bh4);
                MMA_BF16(S[2 * np],     ah, bl4);
                MMA_BF16(S[2 * np],     al, bh4);
                MMA_BF16(S[2 * np + 1], ah, bh4 + 2);
                MMA_BF16(S[2 * np + 1], ah, bl4 + 2);
                MMA_BF16(S[2 * np + 1], al, bh4 + 2);
            }
        }

        // scale + causal mask (diagonal region only)
        const bool dom = (kt >= 2 * qt);
#pragma unroll
        for (int nt = 0; nt < 8; nt++)
#pragma unroll
            for (int q = 0; q < 4; q++) {
                float v = S[nt][q] * scale;
                if (dom) {
                    int col = kt * 64 + nt * 8 + 2 * tig + (q & 1);
                    int row = (q < 2) ? row0 : row1;
                    if (col > row) v = -1e30f;
                }
                S[nt][q] = v;
            }

        // online softmax
        float mx0 = -1e30f, mx1 = -1e30f;
#pragma unroll
        for (int nt = 0; nt < 8; nt++) {
            mx0 = fmaxf(mx0, fmaxf(S[nt][0], S[nt][1]));
            mx1 = fmaxf(mx1, fmaxf(S[nt][2], S[nt][3]));
        }
        mx0 = fmaxf(mx0, __shfl_xor_sync(0xffffffffu, mx0, 1));
        mx0 = fmaxf(mx0, __shfl_xor_sync(0xffffffffu, mx0, 2));
        mx1 = fmaxf(mx1, __shfl_xor_sync(0xffffffffu, mx1, 1));
        mx1 = fmaxf(mx1, __shfl_xor_sync(0xffffffffu, mx1, 2));
        float mn0 = fmaxf(m0, mx0), mn1 = fmaxf(m1, mx1);
        float a0 = __expf(m0 - mn0), a1 = __expf(m1 - mn1);
        m0 = mn0; m1 = mn1;
        float s0 = 0.f, s1 = 0.f;
#pragma unroll
        for (int nt = 0; nt < 8; nt++) {
            S[nt][0] = __expf(S[nt][0] - mn0); s0 += S[nt][0];
            S[nt][1] = __expf(S[nt][1] - mn0); s0 += S[nt][1];
            S[nt][2] = __expf(S[nt][2] - mn1); s1 += S[nt][2];
            S[nt][3] = __expf(S[nt][3] - mn1); s1 += S[nt][3];
        }
        s0 += __shfl_xor_sync(0xffffffffu, s0, 1);
        s0 += __shfl_xor_sync(0xffffffffu, s0, 2);
        s1 += __shfl_xor_sync(0xffffffffu, s1, 1);
        s1 += __shfl_xor_sync(0xffffffffu, s1, 2);
        l0 = l0 * a0 + s0;
        l1 = l1 * a1 + s1;
#pragma unroll
        for (int nt = 0; nt < 16; nt++) {
            O[nt][0] *= a0; O[nt][1] *= a0;
            O[nt][2] *= a1; O[nt][3] *= a1;
        }

        // O += P V : P fp16 (single), V fp16 hi/lo -> 2 MMAs per tile pair
#pragma unroll
        for (int j = 0; j < 4; j++) {
            uint32_t pa[4];
            {
                __half2 h;
                h = __floats2half2_rn(S[2 * j][0],     S[2 * j][1]);     pa[0] = *(uint32_t*)&h;
                h = __floats2half2_rn(S[2 * j][2],     S[2 * j][3]);     pa[1] = *(uint32_t*)&h;
                h = __floats2half2_rn(S[2 * j + 1][0], S[2 * j + 1][1]); pa[2] = *(uint32_t*)&h;
                h = __floats2half2_rn(S[2 * j + 1][2], S[2 * j + 1][3]); pa[3] = *(uint32_t*)&h;
            }
#pragma unroll
            for (int np = 0; np < 8; np++) {
                int vr = j * 16 + (lane & 15);
                int vc = 2 * np + (lane >> 4);
                uint32_t va = sk + 32768 + vr * 256 + ((vc ^ (vr & 7)) << 4);
                uint32_t vh4[4], vl4[4];
                LDMATRIX_X4_T(vh4[0], vh4[1], vh4[2], vh4[3], va);
                LDMATRIX_X4_T(vl4[0], vl4[1], vl4[2], vl4[3], va + 16384);
                MMA_FP16(O[2 * np],     pa, vh4);
                MMA_FP16(O[2 * np],     pa, vl4);
                MMA_FP16(O[2 * np + 1], pa, vh4 + 2);
                MMA_FP16(O[2 * np + 1], pa, vl4 + 2);
            }
        }
    }

    // Epilogue: normalize, stage to smem, write ctx hi/lo bf16
    __syncthreads();                          // all warps done with KV smem
    float li0 = 1.0f / l0, li1 = 1.0f / l1;
    float* stg = (float*)smem;
    {
        int r0l = w * 16 + g, r1l = r0l + 8;
#pragma unroll
        for (int nt = 0; nt < 16; nt++) {
            float2 v0 = make_float2(O[nt][0] * li0, O[nt][1] * li0);
            float2 v1 = make_float2(O[nt][2] * li1, O[nt][3] * li1);
            *(float2*)&stg[r0l * 132 + nt * 8 + 2 * tig] = v0;
            *(float2*)&stg[r1l * 132 + nt * 8 + 2 * tig] = v1;
        }
    }
    __syncthreads();
    {
        int r = tid >> 1, ch = (tid & 1) * 64;
        int b = bh >> 4, h = bh & 15;
        size_t base = ((size_t)(b * T_ + q0 + r)) * C_ + h * 128 + ch;
#pragma unroll
        for (int c = 0; c < 64; c += 2) {
            float x = stg[r * 132 + ch + c], y = stg[r * 132 + ch + c + 1];
            __nv_bfloat162 hh = __floats2bfloat162_rn(x, y);
            float hx = __low2float(hh), hy = __high2float(hh);
            __nv_bfloat162 ll = __floats2bfloat162_rn(x - hx, y - hy);
            *(__nv_bfloat162*)&gcx_hi[base + c] = hh;
            *(__nv_bfloat162*)&gcx_lo[base + c] = ll;
        }
    }
}

// ---------------------------------------------------------------------------
extern "C" void kernel_launch(void* const* d_in, const int* in_sizes, int n_in,
                              void* d_out, int out_size)
{
    const float* x = nullptr; const float* w_qkv = nullptr;
    const float* w_proj = nullptr; const float* b_proj = nullptr;
    for (int i = 0; i < n_in; i++) {
        switch (in_sizes[i]) {
            case M_ * C_:  x      = (const float*)d_in[i]; break;
            case C_ * N3_: w_qkv  = (const float*)d_in[i]; break;
            case C_ * C_:  w_proj = (const float*)d_in[i]; break;
            case C_:       b_proj = (const float*)d_in[i]; break;
        }
    }
    float* out = (float*)d_out;

    void *p_qkv, *p_xh, *p_xl, *p_cxh, *p_cxl;
    void *p_wqh, *p_wql, *p_wph, *p_wpl;
    cudaGetSymbolAddress(&p_qkv, g_qkv);
    cudaGetSymbolAddress(&p_xh,  gx_hi);  cudaGetSymbolAddress(&p_xl,  gx_lo);
    cudaGetSymbolAddress(&p_cxh, gcx_hi); cudaGetSymbolAddress(&p_cxl, gcx_lo);
    cudaGetSymbolAddress(&p_wqh, gwq_hi); cudaGetSymbolAddress(&p_wql, gwq_lo);
    cudaGetSymbolAddress(&p_wph, gwp_hi); cudaGetSymbolAddress(&p_wpl, gwp_lo);

    cudaFuncSetAttribute(gemm_mma_kernel,
                         cudaFuncAttributeMaxDynamicSharedMemorySize, GEMM_SMEM);
    cudaFuncSetAttribute(attn_mma_kernel,
                         cudaFuncAttributeMaxDynamicSharedMemorySize, ATTN_SMEM);

    // 1) operand prep
    split_kernel<<<(M_ * C_ / 4 + 255) / 256, 256>>>(
        x, (__nv_bfloat16*)p_xh, (__nv_bfloat16*)p_xl, M_ * C_ / 4);
    transpose_split_kernel<<<dim3(N3_ / 32, C_ / 32), dim3(32, 8)>>>(
        w_qkv, (__nv_bfloat16*)p_wqh, (__nv_bfloat16*)p_wql, C_, N3_);
    transpose_split_kernel<<<dim3(C_ / 32, C_ / 32), dim3(32, 8)>>>(
        w_proj, (__nv_bfloat16*)p_wph, (__nv_bfloat16*)p_wpl, C_, C_);

    // 2) QKV GEMM (HMMA): [8192,2048] x [6144,2048]^T
    gemm_mma_kernel<<<dim3(N3_ / 128, M_ / 128), 256, GEMM_SMEM>>>(
        (const __nv_bfloat16*)p_xh, (const __nv_bfloat16*)p_xl,
        (const __nv_bfloat16*)p_wqh, (const __nv_bfloat16*)p_wql,
        (float*)p_qkv, nullptr, N3_, C_);

    // 3) RoPE -> bf16 hi/lo q/k, fp16 hi/lo v
    rope_table_kernel<<<(T_ * 64 + 255) / 256, 256>>>();
    rope_kernel<<<(BH_ * T_ * D_) / 256, 256>>>();

    // 4) causal flash attention on HMMA (writes ctx hi/lo directly)
    attn_mma_kernel<<<dim3(T_ / 128, BH_), 256, ATTN_SMEM>>>();

    // 5) projection GEMM (HMMA) + bias -> out
    gemm_mma_kernel<<<dim3(C_ / 128, M_ / 128), 256, GEMM_SMEM>>>(
        (const __nv_bfloat16*)p_cxh, (const __nv_bfloat16*)p_cxl,
        (const __nv_bfloat16*)p_wph, (const __nv_bfloat16*)p_wpl,
        out, b_proj, C_, C_);
}

// round 6
// speedup vs baseline: 5.0988x; 1.4444x over previous
#include <cuda_runtime.h>
#include <cuda_bf16.h>
#include <cuda_fp16.h>
#include <math.h>
#include <stdint.h>

// Problem constants
#define B_   4
#define T_   2048
#define C_   2048
#define H_   16
#define D_   128
#define BH_  (B_ * H_)        // 64
#define M_   (B_ * T_)        // 8192
#define N3_  (3 * C_)         // 6144

// ============================ helpers ======================================
__device__ __forceinline__ uint32_t smem_u32(const void* p) {
    uint32_t a;
    asm("{ .reg .u64 t; cvta.to.shared.u64 t, %1; cvt.u32.u64 %0, t; }"
        : "=r"(a) : "l"(p));
    return a;
}
#define CP_ASYNC16(saddr, gptr) \
    asm volatile("cp.async.cg.shared.global [%0], [%1], 16;" \
                 :: "r"(saddr), "l"(gptr) : "memory")
#define CP_COMMIT() asm volatile("cp.async.commit_group;" ::: "memory")
#define CP_WAIT_GROUP(n) asm volatile("cp.async.wait_group %0;" :: "n"(n) : "memory")

#define LDMATRIX_X4(r0, r1, r2, r3, addr) \
    asm volatile("ldmatrix.sync.aligned.m8n8.x4.shared.b16 {%0,%1,%2,%3}, [%4];" \
                 : "=r"(r0), "=r"(r1), "=r"(r2), "=r"(r3) : "r"(addr))
#define LDMATRIX_X4_T(r0, r1, r2, r3, addr) \
    asm volatile("ldmatrix.sync.aligned.m8n8.x4.trans.shared.b16 {%0,%1,%2,%3}, [%4];" \
                 : "=r"(r0), "=r"(r1), "=r"(r2), "=r"(r3) : "r"(addr))
#define LDMATRIX_X2(r0, r1, addr) \
    asm volatile("ldmatrix.sync.aligned.m8n8.x2.shared.b16 {%0,%1}, [%2];" \
                 : "=r"(r0), "=r"(r1) : "r"(addr))
#define MMA_FP16(c, a, b) \
    asm volatile("mma.sync.aligned.m16n8k16.row.col.f32.f16.f16.f32 " \
                 "{%0,%1,%2,%3}, {%4,%5,%6,%7}, {%8,%9}, {%0,%1,%2,%3};" \
                 : "+f"((c)[0]), "+f"((c)[1]), "+f"((c)[2]), "+f"((c)[3]) \
                 : "r"((a)[0]), "r"((a)[1]), "r"((a)[2]), "r"((a)[3]), \
                   "r"((b)[0]), "r"((b)[1]))

// ---------------- scratch (device globals; no allocation allowed) ----------
__device__ float g_qkv[M_ * N3_];          // [8192, 6144] fp32
__device__ float g_cos[T_ * 64];
__device__ float g_sin[T_ * 64];
// fp16 operands: A-side split hi/lo (exact), B-side single (rounded)
__device__ __half gx_hi[M_ * C_],  gx_lo[M_ * C_];     // activations [M,K]
__device__ __half gcx_hi[M_ * C_], gcx_lo[M_ * C_];    // ctx [M,K]
__device__ __half gwq[N3_ * C_];                       // W_qkv^T [N,K] single
__device__ __half gwp[C_ * C_];                        // W_proj^T [N,K] single
// attention operands [BH, T, D]
__device__ __half gq_hi[BH_ * T_ * D_], gq_lo[BH_ * T_ * D_];
__device__ __half gk_s[BH_ * T_ * D_];                 // K single fp16
__device__ __half gv_hi[BH_ * T_ * D_], gv_lo[BH_ * T_ * D_];

// ---------------------------------------------------------------------------
// split fp32 -> (hi, lo) fp16, elementwise (vectorized by 4)
// ---------------------------------------------------------------------------
__global__ void __launch_bounds__(256) split_kernel(
    const float* __restrict__ in, __half* __restrict__ hi,
    __half* __restrict__ lo, int n4)
{
    int i = blockIdx.x * 256 + threadIdx.x;
    if (i >= n4) return;
    float4 v = ((const float4*)in)[i];
    __half h0 = __float2half_rn(v.x), h1 = __float2half_rn(v.y);
    __half h2 = __float2half_rn(v.z), h3 = __float2half_rn(v.w);
    __half l0 = __float2half_rn(v.x - __half2float(h0));
    __half l1 = __float2half_rn(v.y - __half2float(h1));
    __half l2 = __float2half_rn(v.z - __half2float(h2));
    __half l3 = __float2half_rn(v.w - __half2float(h3));
    __half2* hp = (__half2*)hi;
    __half2* lp = (__half2*)lo;
    hp[i * 2 + 0] = __half2(h0, h1);
    hp[i * 2 + 1] = __half2(h2, h3);
    lp[i * 2 + 0] = __half2(l0, l1);
    lp[i * 2 + 1] = __half2(l2, l3);
}

// ---------------------------------------------------------------------------
// transpose + round: W[K,N] fp32 -> Wh[N,K] fp16 (single)
// ---------------------------------------------------------------------------
__global__ void __launch_bounds__(256) transpose_h_kernel(
    const float* __restrict__ W, __half* __restrict__ Th, int K, int N)
{
    __shared__ float t[32][33];
    int bn = blockIdx.x * 32;
    int bk = blockIdx.y * 32;
    int x = threadIdx.x, y = threadIdx.y;       // 32 x 8
#pragma unroll
    for (int i = 0; i < 32; i += 8)
        t[y + i][x] = W[(size_t)(bk + y + i) * N + bn + x];
    __syncthreads();
#pragma unroll
    for (int i = 0; i < 32; i += 8) {
        float v = t[x][y + i];                  // = W[bk+x][bn+y+i]
        Th[(size_t)(bn + y + i) * K + bk + x] = __float2half_rn(v);
    }
}

// ---------------------------------------------------------------------------
// HMMA GEMM: C[M,N] = A[M,K] @ B[N,K]^T, fp16 x2 (Ah*B + Al*B; A exact, B rounded)
// CTA 128x128, BK=64, 2-stage cp.async, 8 warps (2x4), 2 CTAs/SM.
// ---------------------------------------------------------------------------
#define STG_BYTES 49152              // AH 16K + AL 16K + B 16K
#define OFF_AH 0
#define OFF_AL 16384
#define OFF_B  32768
#define GEMM_SMEM (2 * STG_BYTES)    // 96 KB

__device__ __forceinline__ void gemm_load_stage(
    uint32_t sb, int stage,
    const __half* __restrict__ Ah, const __half* __restrict__ Al,
    const __half* __restrict__ Bh,
    int row0, int col0, int kb, int K, int tid)
{
    uint32_t st = sb + stage * STG_BYTES;
    const int k0 = kb * 64;
#pragma unroll
    for (int u = 0; u < 4; u++) {
        int idx = u * 256 + tid;                 // 1024 16B chunks per operand
        int r = idx >> 3, c = idx & 7;
        uint32_t sw = (uint32_t)(r * 128 + ((c ^ (r & 7)) << 4));
        size_t ga = (size_t)(row0 + r) * K + k0 + c * 8;
        size_t gb = (size_t)(col0 + r) * K + k0 + c * 8;
        CP_ASYNC16(st + OFF_AH + sw, Ah + ga);
        CP_ASYNC16(st + OFF_AL + sw, Al + ga);
        CP_ASYNC16(st + OFF_B  + sw, Bh + gb);
    }
}

__global__ void __launch_bounds__(256, 2) gemm_mma_kernel(
    const __half* __restrict__ Ah, const __half* __restrict__ Al,
    const __half* __restrict__ Bh,
    float* __restrict__ Cout, const float* __restrict__ bias, int N, int K)
{
    extern __shared__ __align__(1024) char smem[];
    const uint32_t sb = smem_u32(smem);
    const int tid = threadIdx.x;
    const int wid = tid >> 5, lane = tid & 31;
    const int wr = wid >> 2, wc = wid & 3;       // warp grid 2 x 4
    const int col0 = blockIdx.x * 128;
    const int row0 = blockIdx.y * 128;
    const int NK = K / 64;

    float acc[4][4][4];
#pragma unroll
    for (int i = 0; i < 4; i++)
#pragma unroll
        for (int j = 0; j < 4; j++)
#pragma unroll
            for (int k = 0; k < 4; k++) acc[i][j][k] = 0.f;

    gemm_load_stage(sb, 0, Ah, Al, Bh, row0, col0, 0, K, tid);
    CP_COMMIT();

    const int a_row = wr * 64 + (lane & 15);
    const int b_row = wc * 32 + (lane & 7);
    const int a_cg  = (lane >> 4);
    const int b_cg  = ((lane >> 3) & 1);

    for (int kb = 0; kb < NK; kb++) {
        CP_WAIT_GROUP(0);
        __syncthreads();
        if (kb + 1 < NK)
            gemm_load_stage(sb, (kb + 1) & 1, Ah, Al, Bh, row0, col0, kb + 1, K, tid);
        CP_COMMIT();

        uint32_t st = sb + (kb & 1) * STG_BYTES;
#pragma unroll
        for (int ks = 0; ks < 4; ks++) {
            uint32_t ah[4][4], al[4][4], bf[4][2];
#pragma unroll
            for (int mt = 0; mt < 4; mt++) {
                int r = a_row + mt * 16;
                int c = ks * 2 + a_cg;
                uint32_t ad = st + (uint32_t)(r * 128 + ((c ^ (r & 7)) << 4));
                LDMATRIX_X4(ah[mt][0], ah[mt][1], ah[mt][2], ah[mt][3], ad + OFF_AH);
                LDMATRIX_X4(al[mt][0], al[mt][1], al[mt][2], al[mt][3], ad + OFF_AL);
            }
#pragma unroll
            for (int nt = 0; nt < 4; nt++) {
                int n = b_row + nt * 8;
                int c = ks * 2 + b_cg;
                uint32_t bd = st + (uint32_t)(n * 128 + ((c ^ (n & 7)) << 4));
                LDMATRIX_X2(bf[nt][0], bf[nt][1], bd + OFF_B);
            }
#pragma unroll
            for (int mt = 0; mt < 4; mt++)
#pragma unroll
                for (int nt = 0; nt < 4; nt++) {
                    MMA_FP16(acc[mt][nt], ah[mt], bf[nt]);
                    MMA_FP16(acc[mt][nt], al[mt], bf[nt]);
                }
        }
    }

    const int er = lane >> 2;
    const int ec = (lane & 3) * 2;
#pragma unroll
    for (int mt = 0; mt < 4; mt++) {
        int row = row0 + wr * 64 + mt * 16 + er;
#pragma unroll
        for (int nt = 0; nt < 4; nt++) {
            int col = col0 + wc * 32 + nt * 8 + ec;
            float b0 = 0.f, b1 = 0.f;
            if (bias) { b0 = bias[col]; b1 = bias[col + 1]; }
            float2 v0, v1;
            v0.x = acc[mt][nt][0] + b0; v0.y = acc[mt][nt][1] + b1;
            v1.x = acc[mt][nt][2] + b0; v1.y = acc[mt][nt][3] + b1;
            *(float2*)&Cout[(size_t)row * N + col] = v0;
            *(float2*)&Cout[(size_t)(row + 8) * N + col] = v1;
        }
    }
}

// ---------------------------------------------------------------------------
// RoPE table
// ---------------------------------------------------------------------------
__global__ void rope_table_kernel()
{
    int g = blockIdx.x * blockDim.x + threadIdx.x;
    if (g >= T_ * 64) return;
    int t = g >> 6, i = g & 63;
    double invf = pow(10000.0, -(double)i / 64.0);
    float  angf = (float)t * (float)invf;
    double ang  = (double)angf;
    g_cos[g] = (float)cos(ang);
    g_sin[g] = (float)sin(ang);
}

// ---------------------------------------------------------------------------
// RoPE + split/transpose: g_qkv[B,T,3C] -> q fp16 hi/lo, k fp16 single, v fp16 hi/lo
// ---------------------------------------------------------------------------
__global__ void __launch_bounds__(256) rope_kernel()
{
    int g = blockIdx.x * 256 + threadIdx.x;
    int d  = g & 127;
    int t  = (g >> 7) & 2047;
    int bh = g >> 18;
    int b  = bh >> 4, h = bh & 15;

    size_t src = ((size_t)(b * T_ + t)) * N3_ + h * D_ + d;
    int dp = (d + 64) & 127;
    size_t srcp = src - d + dp;

    float qa = g_qkv[src];
    float ka = g_qkv[src + C_];
    float va = g_qkv[src + 2 * C_];
    float qb = g_qkv[srcp];
    float kb = g_qkv[srcp + C_];

    float sgn = (d < 64) ? -1.f : 1.f;
    int i = d & 63;
    float c = g_cos[t * 64 + i];
    float s = g_sin[t * 64 + i];

    float qr = qa * c + sgn * qb * s;
    float kr = ka * c + sgn * kb * s;

    size_t dst = ((size_t)bh * T_ + t) * D_ + d;
    __half qh = __float2half_rn(qr);
    gq_hi[dst] = qh; gq_lo[dst] = __float2half_rn(qr - __half2float(qh));
    gk_s[dst] = __float2half_rn(kr);
    __half vh = __float2half_rn(va);
    gv_hi[dst] = vh; gv_lo[dst] = __float2half_rn(va - __half2float(vh));
}

// ---------------------------------------------------------------------------
// Flash attention (causal) on HMMA, all fp16.
// QK: (Qh+Ql) x K_single = 2 MMAs.  PV: P_single x (Vh+Vl) = 2 MMAs.
// CTA = (128 q rows, one bh); 8 warps of 16 rows; K-tiles of 64 keys;
// 2-stage cp.async, 1 sync/iter. Writes ctx hi/lo fp16 directly.
// ---------------------------------------------------------------------------
#define KV_STG 49152                  // K 16K + Vh 16K + Vl 16K
#define ATTN_SMEM (65536 + 2 * KV_STG)   // Q 64K + 2 KV stages = 160 KB

__device__ __forceinline__ void attn_load_kv(
    uint32_t skv, int stage,
    const __half* __restrict__ ks, const __half* __restrict__ vh,
    const __half* __restrict__ vl, int k0, int tid)
{
    uint32_t st = skv + stage * KV_STG;
    const __half* srcs[3] = {ks, vh, vl};
#pragma unroll
    for (int u = 0; u < 12; u++) {
        int idx = u * 256 + tid;
        int a = u >> 2;                     // constant per unrolled u
        int rem = idx & 1023;
        int r = rem >> 4, c = rem & 15;
        uint32_t dst = st + a * 16384 + r * 256 + ((c ^ (r & 7)) << 4);
        CP_ASYNC16(dst, srcs[a] + (size_t)(k0 + r) * D_ + c * 8);
    }
}

__global__ void __launch_bounds__(256, 1) attn_mma_kernel()
{
    extern __shared__ __align__(1024) char smem[];
    const uint32_t sb = smem_u32(smem);
    const int tid = threadIdx.x;
    const int w = tid >> 5, lane = tid & 31;
    const int g = lane >> 2, tig = lane & 3;
    const int qt = (int)gridDim.x - 1 - (int)blockIdx.x;   // heavy tiles first
    const int bh = blockIdx.y;
    const int q0 = qt * 128;
    const int NT = 2 * (qt + 1);

    const size_t hb = (size_t)bh * T_ * D_;
    const __half* Qh = gq_hi + hb;
    const __half* Ql = gq_lo + hb;
    const __half* Ks = gk_s + hb;
    const __half* Vh = gv_hi + hb;
    const __half* Vl = gv_lo + hb;

    const uint32_t sq = sb;
    const uint32_t skv = sb + 65536;

    // Load Q tile (hi/lo), rows 256B swizzled; + KV stage 0 — one group
#pragma unroll
    for (int u = 0; u < 16; u++) {
        int idx = u * 256 + tid;
        int a = u >> 3;                    // 0: hi, 1: lo
        int rem = idx & 2047;
        int r = rem >> 4, c = rem & 15;
        uint32_t dst = sq + a * 32768 + r * 256 + ((c ^ (r & 7)) << 4);
        const __half* src = (a == 0 ? Qh : Ql) + (size_t)(q0 + r) * D_ + c * 8;
        CP_ASYNC16(dst, src);
    }
    attn_load_kv(skv, 0, Ks, Vh, Vl, 0, tid);
    CP_COMMIT();

    float O[16][4];
#pragma unroll
    for (int i = 0; i < 16; i++)
#pragma unroll
        for (int j = 0; j < 4; j++) O[i][j] = 0.f;
    float m0 = -1e30f, m1 = -1e30f, l0 = 0.f, l1 = 0.f;
    const float scale = 0.08838834764831845f;
    const int row0 = q0 + w * 16 + g;
    const int row1 = row0 + 8;

    for (int kt = 0; kt < NT; kt++) {
        CP_WAIT_GROUP(0);
        __syncthreads();
        if (kt + 1 < NT)
            attn_load_kv(skv, (kt + 1) & 1, Ks, Vh, Vl, (kt + 1) * 64, tid);
        CP_COMMIT();
        const uint32_t sk = skv + (kt & 1) * KV_STG;

        // S = Q K^T (Qh + Ql) x K
        float S[8][4];
#pragma unroll
        for (int i = 0; i < 8; i++)
#pragma unroll
            for (int j = 0; j < 4; j++) S[i][j] = 0.f;

#pragma unroll
        for (int ks = 0; ks < 8; ks++) {
            int qrow = w * 16 + (lane & 15);
            int qc = 2 * ks + (lane >> 4);
            uint32_t qa = sq + qrow * 256 + ((qc ^ (qrow & 7)) << 4);
            uint32_t ah[4], al[4];
            LDMATRIX_X4(ah[0], ah[1], ah[2], ah[3], qa);
            LDMATRIX_X4(al[0], al[1], al[2], al[3], qa + 32768);
#pragma unroll
            for (int np = 0; np < 4; np++) {
                int kr = np * 16 + (lane & 7) + ((lane >> 4) << 3);
                int kc = 2 * ks + ((lane >> 3) & 1);
                uint32_t ka = sk + kr * 256 + ((kc ^ (kr & 7)) << 4);
                uint32_t kf[4];
                LDMATRIX_X4(kf[0], kf[1], kf[2], kf[3], ka);
                MMA_FP16(S[2 * np],     ah, kf);
                MMA_FP16(S[2 * np],     al, kf);
                MMA_FP16(S[2 * np + 1], ah, kf + 2);
                MMA_FP16(S[2 * np + 1], al, kf + 2);
            }
        }

        // scale + causal mask (diagonal region only)
        const bool dom = (kt >= 2 * qt);
#pragma unroll
        for (int nt = 0; nt < 8; nt++)
#pragma unroll
            for (int q = 0; q < 4; q++) {
                float v = S[nt][q] * scale;
                if (dom) {
                    int col = kt * 64 + nt * 8 + 2 * tig + (q & 1);
                    int row = (q < 2) ? row0 : row1;
                    if (col > row) v = -1e30f;
                }
                S[nt][q] = v;
            }

        // online softmax
        float mx0 = -1e30f, mx1 = -1e30f;
#pragma unroll
        for (int nt = 0; nt < 8; nt++) {
            mx0 = fmaxf(mx0, fmaxf(S[nt][0], S[nt][1]));
            mx1 = fmaxf(mx1, fmaxf(S[nt][2], S[nt][3]));
        }
        mx0 = fmaxf(mx0, __shfl_xor_sync(0xffffffffu, mx0, 1));
        mx0 = fmaxf(mx0, __shfl_xor_sync(0xffffffffu, mx0, 2));
        mx1 = fmaxf(mx1, __shfl_xor_sync(0xffffffffu, mx1, 1));
        mx1 = fmaxf(mx1, __shfl_xor_sync(0xffffffffu, mx1, 2));
        float mn0 = fmaxf(m0, mx0), mn1 = fmaxf(m1, mx1);
        float a0 = __expf(m0 - mn0), a1 = __expf(m1 - mn1);
        m0 = mn0; m1 = mn1;
        float s0 = 0.f, s1 = 0.f;
#pragma unroll
        for (int nt = 0; nt < 8; nt++) {
            S[nt][0] = __expf(S[nt][0] - mn0); s0 += S[nt][0];
            S[nt][1] = __expf(S[nt][1] - mn0); s0 += S[nt][1];
            S[nt][2] = __expf(S[nt][2] - mn1); s1 += S[nt][2];
            S[nt][3] = __expf(S[nt][3] - mn1); s1 += S[nt][3];
        }
        s0 += __shfl_xor_sync(0xffffffffu, s0, 1);
        s0 += __shfl_xor_sync(0xffffffffu, s0, 2);
        s1 += __shfl_xor_sync(0xffffffffu, s1, 1);
        s1 += __shfl_xor_sync(0xffffffffu, s1, 2);
        l0 = l0 * a0 + s0;
        l1 = l1 * a1 + s1;
#pragma unroll
        for (int nt = 0; nt < 16; nt++) {
            O[nt][0] *= a0; O[nt][1] *= a0;
            O[nt][2] *= a1; O[nt][3] *= a1;
        }

        // O += P V : P fp16 single, V fp16 hi/lo
#pragma unroll
        for (int j = 0; j < 4; j++) {
            uint32_t pa[4];
            {
                __half2 h;
                h = __floats2half2_rn(S[2 * j][0],     S[2 * j][1]);     pa[0] = *(uint32_t*)&h;
                h = __floats2half2_rn(S[2 * j][2],     S[2 * j][3]);     pa[1] = *(uint32_t*)&h;
                h = __floats2half2_rn(S[2 * j + 1][0], S[2 * j + 1][1]); pa[2] = *(uint32_t*)&h;
                h = __floats2half2_rn(S[2 * j + 1][2], S[2 * j + 1][3]); pa[3] = *(uint32_t*)&h;
            }
#pragma unroll
            for (int np = 0; np < 8; np++) {
                int vr = j * 16 + (lane & 15);
                int vc = 2 * np + (lane >> 4);
                uint32_t va = sk + 16384 + vr * 256 + ((vc ^ (vr & 7)) << 4);
                uint32_t vh4[4], vl4[4];
                LDMATRIX_X4_T(vh4[0], vh4[1], vh4[2], vh4[3], va);
                LDMATRIX_X4_T(vl4[0], vl4[1], vl4[2], vl4[3], va + 16384);
                MMA_FP16(O[2 * np],     pa, vh4);
                MMA_FP16(O[2 * np],     pa, vl4);
                MMA_FP16(O[2 * np + 1], pa, vh4 + 2);
                MMA_FP16(O[2 * np + 1], pa, vl4 + 2);
            }
        }
    }

    // Epilogue: normalize, stage to smem, write ctx hi/lo fp16
    __syncthreads();                          // all warps done with KV smem
    float li0 = 1.0f / l0, li1 = 1.0f / l1;
    float* stg = (float*)smem;
    {
        int r0l = w * 16 + g, r1l = r0l + 8;
#pragma unroll
        for (int nt = 0; nt < 16; nt++) {
            float2 v0 = make_float2(O[nt][0] * li0, O[nt][1] * li0);
            float2 v1 = make_float2(O[nt][2] * li1, O[nt][3] * li1);
            *(float2*)&stg[r0l * 132 + nt * 8 + 2 * tig] = v0;
            *(float2*)&stg[r1l * 132 + nt * 8 + 2 * tig] = v1;
        }
    }
    __syncthreads();
    {
        int r = tid >> 1, ch = (tid & 1) * 64;
        int b = bh >> 4, h = bh & 15;
        size_t base = ((size_t)(b * T_ + q0 + r)) * C_ + h * 128 + ch;
#pragma unroll
        for (int c = 0; c < 64; c += 2) {
            float x = stg[r * 132 + ch + c], y = stg[r * 132 + ch + c + 1];
            __half hx = __float2half_rn(x), hy = __float2half_rn(y);
            __half lx = __float2half_rn(x - __half2float(hx));
            __half ly = __float2half_rn(y - __half2float(hy));
            *(__half2*)&gcx_hi[base + c] = __half2(hx, hy);
            *(__half2*)&gcx_lo[base + c] = __half2(lx, ly);
        }
    }
}

// ---------------------------------------------------------------------------
extern "C" void kernel_launch(void* const* d_in, const int* in_sizes, int n_in,
                              void* d_out, int out_size)
{
    const float* x = nullptr; const float* w_qkv = nullptr;
    const float* w_proj = nullptr; const float* b_proj = nullptr;
    for (int i = 0; i < n_in; i++) {
        switch (in_sizes[i]) {
            case M_ * C_:  x      = (const float*)d_in[i]; break;
            case C_ * N3_: w_qkv  = (const float*)d_in[i]; break;
            case C_ * C_:  w_proj = (const float*)d_in[i]; break;
            case C_:       b_proj = (const float*)d_in[i]; break;
        }
    }
    float* out = (float*)d_out;

    void *p_qkv, *p_xh, *p_xl, *p_cxh, *p_cxl, *p_wq, *p_wp;
    cudaGetSymbolAddress(&p_qkv, g_qkv);
    cudaGetSymbolAddress(&p_xh,  gx_hi);  cudaGetSymbolAddress(&p_xl,  gx_lo);
    cudaGetSymbolAddress(&p_cxh, gcx_hi); cudaGetSymbolAddress(&p_cxl, gcx_lo);
    cudaGetSymbolAddress(&p_wq,  gwq);    cudaGetSymbolAddress(&p_wp,  gwp);

    cudaFuncSetAttribute(gemm_mma_kernel,
                         cudaFuncAttributeMaxDynamicSharedMemorySize, GEMM_SMEM);
    cudaFuncSetAttribute(attn_mma_kernel,
                         cudaFuncAttributeMaxDynamicSharedMemorySize, ATTN_SMEM);

    // 1) operand prep
    split_kernel<<<(M_ * C_ / 4 + 255) / 256, 256>>>(
        x, (__half*)p_xh, (__half*)p_xl, M_ * C_ / 4);
    transpose_h_kernel<<<dim3(N3_ / 32, C_ / 32), dim3(32, 8)>>>(
        w_qkv, (__half*)p_wq, C_, N3_);
    transpose_h_kernel<<<dim3(C_ / 32, C_ / 32), dim3(32, 8)>>>(
        w_proj, (__half*)p_wp, C_, C_);

    // 2) QKV GEMM (HMMA fp16 x2): [8192,2048] x [6144,2048]^T
    gemm_mma_kernel<<<dim3(N3_ / 128, M_ / 128), 256, GEMM_SMEM>>>(
        (const __half*)p_xh, (const __half*)p_xl, (const __half*)p_wq,
        (float*)p_qkv, nullptr, N3_, C_);

    // 3) RoPE -> fp16 operands
    rope_table_kernel<<<(T_ * 64 + 255) / 256, 256>>>();
    rope_kernel<<<(BH_ * T_ * D_) / 256, 256>>>();

    // 4) causal flash attention on HMMA (writes ctx hi/lo directly)
    attn_mma_kernel<<<dim3(T_ / 128, BH_), 256, ATTN_SMEM>>>();

    // 5) projection GEMM (HMMA fp16 x2) + bias -> out
    gemm_mma_kernel<<<dim3(C_ / 128, M_ / 128), 256, GEMM_SMEM>>>(
        (const __half*)p_cxh, (const __half*)p_cxl, (const __half*)p_wp,
        out, b_proj, C_, C_);
}